// round 12
// baseline (speedup 1.0000x reference)
#include <cuda_runtime.h>
#include <cuda_bf16.h>
#include <stdint.h>
#include <math.h>

#define NB 4096
#define NP 4096
#define NF 1024
#define SHRINK 0.25f
#define LR 0.1f
#define EPS 1e-8f
#define WD 1e-2f
#define STEPS 50

#if defined(__CUDA_ARCH_FEAT_SM103_ALL) || defined(__CUDA_ARCH_FEAT_SM100_ALL) || \
    defined(__CUDA_ARCH_FEAT_SM101_ALL) || defined(__CUDA_ARCH_FEAT_SM120_ALL)
#define TC_OK 1
#else
#define TC_OK 0
#endif

#define NTHR 256
#define BN 128

static const size_t NBNF = (size_t)NB * NF;

// ---------------- persistent device state ----------------------------------
__device__ float g_u[(size_t)NB * NF];
__device__ float g_m[(size_t)NB * NF];
__device__ float g_v[(size_t)NB * NF];
__device__ float g_excite[(size_t)NB * NF];
__device__ __nv_bfloat16 g_acth[2][(size_t)NB * NF];
__device__ __nv_bfloat16 g_actl[2][(size_t)NB * NF];
__device__ __nv_bfloat16 g_imgh[(size_t)NB * NP];
__device__ __nv_bfloat16 g_imgl[(size_t)NB * NP];
__device__ __nv_bfloat16 g_phih[(size_t)NP * NF];
__device__ __nv_bfloat16 g_phil[(size_t)NP * NF];
__device__ __nv_bfloat16 g_phith[(size_t)NF * NP];
__device__ __nv_bfloat16 g_phitl[(size_t)NF * NP];
__device__ __nv_bfloat16 g_Gh[(size_t)NF * NF];
__device__ __nv_bfloat16 g_Gl[(size_t)NF * NF];
__device__ unsigned int g_bar;   // grid-barrier counter (reset each call)

// ---------------- PTX helpers ----------------------------------------------
__device__ __forceinline__ uint32_t smem_u32(const void* p) {
    uint32_t a;
    asm("{ .reg .u64 t; cvta.to.shared.u64 t, %1; cvt.u32.u64 %0, t; }"
        : "=r"(a) : "l"(p));
    return a;
}
__device__ __forceinline__ uint32_t elect_one() {
    uint32_t p;
    asm volatile("{\n\t.reg .pred p;\n\telect.sync _|p, 0xFFFFFFFF;\n\t"
                 "selp.b32 %0, 1, 0, p;\n\t}" : "=r"(p));
    return p;
}
__device__ __forceinline__ void cp_async16(uint32_t dst, const void* src) {
    asm volatile("cp.async.cg.shared.global [%0], [%1], 16;\n" :: "r"(dst), "l"(src));
}
__device__ __forceinline__ void cp_commit() {
    asm volatile("cp.async.commit_group;\n" ::: "memory");
}
// SW64 descriptor: layout=4, version=1 (Blackwell), SBO=32 (512B atom), LBO=1
__device__ __forceinline__ uint64_t mkdesc64(uint32_t addr) {
    return ((uint64_t)4 << 61) | ((uint64_t)1 << 46) | ((uint64_t)32 << 32) |
           ((uint64_t)1 << 16) | ((uint64_t)(addr >> 4) & 0x3FFF);
}
__device__ __forceinline__ void mma_bf16_ss(uint32_t d_tmem, uint64_t a_desc,
                                            uint64_t b_desc, uint32_t idesc, bool acc) {
    uint32_t en = acc ? 1u : 0u;
    asm volatile(
        "{\n\t.reg .pred p;\n\tsetp.ne.u32 p, %5, 0;\n\t"
        "tcgen05.mma.cta_group::1.kind::f16 [%0], %1, %2, %3, {%4,%4,%4,%4}, p;\n\t}"
        :: "r"(d_tmem), "l"(a_desc), "l"(b_desc), "r"(idesc), "r"(0u), "r"(en)
        : "memory");
}
__device__ __forceinline__ void mbar_init(uint32_t a, uint32_t cnt) {
    asm volatile("mbarrier.init.shared.b64 [%0], %1;" :: "r"(a), "r"(cnt) : "memory");
}
__device__ __forceinline__ void mbar_wait(uint32_t a, uint32_t phase) {
    asm volatile(
        "{\n\t.reg .pred P;\n\tLW%=:\n\t"
        "mbarrier.try_wait.parity.shared.b64 P, [%0], %1;\n\t"
        "@!P bra LW%=;\n\t}" :: "r"(a), "r"(phase) : "memory");
}
__device__ __forceinline__ void tc_commit(uint32_t mbar) {
    asm volatile(
        "tcgen05.commit.cta_group::1.mbarrier::arrive::one.shared::cluster.b64 [%0];"
        :: "r"(mbar) : "memory");
}
__device__ __forceinline__ void ldtm32(uint32_t (&r)[32], uint32_t a) {
    asm volatile(
        "tcgen05.ld.sync.aligned.32x32b.x32.b32 "
        "{%0,%1,%2,%3,%4,%5,%6,%7,%8,%9,%10,%11,%12,%13,%14,%15,"
        "%16,%17,%18,%19,%20,%21,%22,%23,%24,%25,%26,%27,%28,%29,%30,%31}, [%32];"
        : "=r"(r[0]), "=r"(r[1]), "=r"(r[2]), "=r"(r[3]), "=r"(r[4]), "=r"(r[5]),
          "=r"(r[6]), "=r"(r[7]), "=r"(r[8]), "=r"(r[9]), "=r"(r[10]), "=r"(r[11]),
          "=r"(r[12]), "=r"(r[13]), "=r"(r[14]), "=r"(r[15]), "=r"(r[16]),
          "=r"(r[17]), "=r"(r[18]), "=r"(r[19]), "=r"(r[20]), "=r"(r[21]),
          "=r"(r[22]), "=r"(r[23]), "=r"(r[24]), "=r"(r[25]), "=r"(r[26]),
          "=r"(r[27]), "=r"(r[28]), "=r"(r[29]), "=r"(r[30]), "=r"(r[31])
        : "r"(a));
}

// smem: [0..4) tmem ptr, [8..32) mbars, [1024..) stages
#define SM_BUF 1024
#define TILE_B 8192                       // 128 rows x 64B (SW64)
#define STG_B (4 * TILE_B)                // Ah, Al, Bh, Bl
#define SMEM_GEMM (SM_BUF + 3 * STG_B)    // 99328 (3-stage) -> 2 CTAs/SM
// idesc: F32 acc, BF16 a/b, N=128, M=128
#define IDESC 0x8200490u

// Load 128-row x 32-col bf16 tile (64B/row), SW64 swizzled. NTHR threads.
__device__ __forceinline__ void load_tile64(uint32_t dst, const __nv_bfloat16* src,
                                            int row0, int ld, int k0, int tid) {
    const char* base = (const char*)(src + (size_t)row0 * ld + k0);
    const size_t ldb = (size_t)ld * 2;
#pragma unroll
    for (int i = 0; i < 512 / NTHR; i++) {
        int cg = tid + i * NTHR;            // 0..511
        int r = cg >> 2, c = cg & 3;        // 128 rows x 4 16B blocks
        uint32_t off = (uint32_t)(r * 64 + c * 16);
        uint32_t sw = off ^ ((off >> 3) & 0x30);
        cp_async16(dst + sw, base + (size_t)r * ldb + c * 16);
    }
}

struct GP {
    const __nv_bfloat16 *Ah, *Al, *Bh, *Bl;
    int ldA, ldB, kIters;
    float* outF; int ldc;             // EPI 0
};

// ---------------------------------------------------------------------------
// Standalone GEMM (R8-proven): 3-stage pipeline, full bf16 split (3 MMAs).
// EPI: 0 = fp32 store, 1 = G (-I, bf16 split out)
// ---------------------------------------------------------------------------
template <int EPI>
__global__ __launch_bounds__(NTHR) void mma_gemm(GP P) {
#if TC_OK
    extern __shared__ char smem[];
    const uint32_t sb = smem_u32(smem);
    const int tid = threadIdx.x;
    const int wid = tid >> 5;
    const int m0 = blockIdx.y * 128, n0 = blockIdx.x * BN;
    const int K = P.kIters;

    if (wid == 0) {
        asm volatile("tcgen05.alloc.cta_group::1.sync.aligned.shared::cta.b32 [%0], %1;"
                     :: "r"(sb + 0), "r"((uint32_t)BN) : "memory");
        asm volatile("tcgen05.relinquish_alloc_permit.cta_group::1.sync.aligned;");
    }
    if (tid < 3) mbar_init(sb + 8 + tid * 8, 1);
    __syncthreads();
    uint32_t tbase;
    asm volatile("ld.shared.b32 %0, [%1];" : "=r"(tbase) : "r"(sb + 0));

#pragma unroll
    for (int c = 0; c < 2; c++) {
        uint32_t s = sb + SM_BUF + c * STG_B;
        int k0 = c * 32;
        load_tile64(s,              P.Ah, m0, P.ldA, k0, tid);
        load_tile64(s + TILE_B,     P.Al, m0, P.ldA, k0, tid);
        load_tile64(s + 2 * TILE_B, P.Bh, n0, P.ldB, k0, tid);
        load_tile64(s + 3 * TILE_B, P.Bl, n0, P.ldB, k0, tid);
        cp_commit();
    }

    for (int k = 0; k < K; k++) {
        if (k + 2 < K) {
            if (k >= 1) mbar_wait(sb + 8 + ((k + 2) % 3) * 8, ((k - 1) / 3) & 1);
            uint32_t s = sb + SM_BUF + ((k + 2) % 3) * STG_B;
            int k0 = (k + 2) * 32;
            load_tile64(s,              P.Ah, m0, P.ldA, k0, tid);
            load_tile64(s + TILE_B,     P.Al, m0, P.ldA, k0, tid);
            load_tile64(s + 2 * TILE_B, P.Bh, n0, P.ldB, k0, tid);
            load_tile64(s + 3 * TILE_B, P.Bl, n0, P.ldB, k0, tid);
            cp_commit();
            asm volatile("cp.async.wait_group 2;\n" ::: "memory");
        } else if (k + 1 < K) {
            asm volatile("cp.async.wait_group 1;\n" ::: "memory");
        } else {
            asm volatile("cp.async.wait_group 0;\n" ::: "memory");
        }
        __syncthreads();
        asm volatile("fence.proxy.async.shared::cta;" ::: "memory");

        if (wid == 0 && elect_one()) {
            uint32_t sc = sb + SM_BUF + (k % 3) * STG_B;
            uint64_t ah = mkdesc64(sc);
            uint64_t al = mkdesc64(sc + TILE_B);
            uint64_t bh = mkdesc64(sc + 2 * TILE_B);
            uint64_t bl = mkdesc64(sc + 3 * TILE_B);
            bool first = (k == 0);
#pragma unroll
            for (int ks = 0; ks < 2; ks++)
                mma_bf16_ss(tbase, ah + ks * 2, bh + ks * 2, IDESC, !(first && ks == 0));
#pragma unroll
            for (int ks = 0; ks < 2; ks++)
                mma_bf16_ss(tbase, ah + ks * 2, bl + ks * 2, IDESC, true);
#pragma unroll
            for (int ks = 0; ks < 2; ks++)
                mma_bf16_ss(tbase, al + ks * 2, bh + ks * 2, IDESC, true);
            tc_commit(sb + 8 + (k % 3) * 8);
        }
    }

    mbar_wait(sb + 8 + ((K - 1) % 3) * 8, ((K - 1) / 3) & 1);
    asm volatile("tcgen05.fence::after_thread_sync;" ::: "memory");

    const int sub = wid & 3;
    const int wg = wid >> 2;
    const int lane = tid & 31;
    const int row = m0 + sub * 32 + lane;

#pragma unroll
    for (int qi = 0; qi < 2; qi++) {
        const int q = wg * 2 + qi;
        uint32_t d[32];
        ldtm32(d, tbase + q * 32);
        asm volatile("tcgen05.wait::ld.sync.aligned;" ::: "memory");
        const int cbase = n0 + q * 32;

        if constexpr (EPI == 0) {
            float4* o = (float4*)(P.outF + (size_t)row * P.ldc + cbase);
#pragma unroll
            for (int jj = 0; jj < 8; jj++) {
                float4 v;
                v.x = __uint_as_float(d[jj * 4 + 0]);
                v.y = __uint_as_float(d[jj * 4 + 1]);
                v.z = __uint_as_float(d[jj * 4 + 2]);
                v.w = __uint_as_float(d[jj * 4 + 3]);
                o[jj] = v;
            }
        } else {
#pragma unroll
            for (int j = 0; j < 32; j++) {
                float val = __uint_as_float(d[j]);
                if (row == cbase + j) val -= 1.0f;
                __nv_bfloat16 h = __float2bfloat16(val);
                __nv_bfloat16 l = __float2bfloat16(val - __bfloat162float(h));
                size_t idx = (size_t)row * NF + cbase + j;
                g_Gh[idx] = h;
                g_Gl[idx] = l;
            }
        }
    }

    asm volatile("tcgen05.fence::before_thread_sync;" ::: "memory");
    __syncthreads();
    if (wid == 0)
        asm volatile("tcgen05.dealloc.cta_group::1.sync.aligned.b32 %0, %1;"
                     :: "r"(tbase), "r"((uint32_t)BN));
#else
    (void)P;
#endif
}

// ---------------------------------------------------------------------------
// Persistent step kernel (steps 4..50, one launch, global grid barrier —
// R10-proven). 3-stage pipeline (97KB smem, 2 CTAs/SM co-resident). At each
// step boundary all stages are free (epilogue waits on the last chunk's
// commit; tensor completion is in-order), so the per-step prologue needs no
// stage waits. Final acts are written directly into d_out.
// ---------------------------------------------------------------------------
__global__ __launch_bounds__(NTHR, 2) void step_persistent(
    const __nv_bfloat16* __restrict__ Gh, const __nv_bfloat16* __restrict__ Gl,
    __nv_bfloat16* __restrict__ ahb, __nv_bfloat16* __restrict__ alb,
    float* __restrict__ actOut)
{
#if TC_OK
    extern __shared__ char smem[];
    const uint32_t sb = smem_u32(smem);
    const int tid = threadIdx.x;
    const int wid = tid >> 5;
    const int m0 = blockIdx.y * 128, n0 = blockIdx.x * BN;
    const size_t NN = (size_t)NB * NF;
    const unsigned nCta = gridDim.x * gridDim.y;

    if (wid == 0) {
        asm volatile("tcgen05.alloc.cta_group::1.sync.aligned.shared::cta.b32 [%0], %1;"
                     :: "r"(sb + 0), "r"((uint32_t)BN) : "memory");
        asm volatile("tcgen05.relinquish_alloc_permit.cta_group::1.sync.aligned;");
    }
    if (tid < 3) mbar_init(sb + 8 + tid * 8, 1);
    __syncthreads();
    uint32_t tbase;
    asm volatile("ld.shared.b32 %0, [%1];" : "=r"(tbase) : "r"(sb + 0));

    unsigned nCommit[3] = {0u, 0u, 0u};

    for (int t = 4; t <= STEPS; t++) {
        const __nv_bfloat16* Ah = ahb + (((t - 1) & 1) ? NN : 0);
        const __nv_bfloat16* Al = alb + (((t - 1) & 1) ? NN : 0);
        __nv_bfloat16* Wh = ahb + ((t & 1) ? NN : 0);
        __nv_bfloat16* Wl = alb + ((t & 1) ? NN : 0);
        const float c1 = 1.0f / (1.0f - powf(0.9f,   (float)t));
        const float c2 = 1.0f / (1.0f - powf(0.999f, (float)t));
        const bool last = (t == STEPS);

        // prologue: chunks 0,1 -> stages 0,1 (all stages free at step start)
#pragma unroll
        for (int c = 0; c < 2; c++) {
            uint32_t s = sb + SM_BUF + c * STG_B;
            int k0 = c * 32;
            load_tile64(s,              Ah, m0, NF, k0, tid);
            load_tile64(s + TILE_B,     Al, m0, NF, k0, tid);
            load_tile64(s + 2 * TILE_B, Gh, n0, NF, k0, tid);
            load_tile64(s + 3 * TILE_B, Gl, n0, NF, k0, tid);
            cp_commit();
        }

        for (int k = 0; k < 32; k++) {
            const int s = k % 3;
            if (k + 2 < 32) {
                const int s2 = (k + 2) % 3;
                if (nCommit[s2] > 0)
                    mbar_wait(sb + 8 + s2 * 8, (nCommit[s2] - 1) & 1);
                uint32_t sa = sb + SM_BUF + s2 * STG_B;
                int k0 = (k + 2) * 32;
                load_tile64(sa,              Ah, m0, NF, k0, tid);
                load_tile64(sa + TILE_B,     Al, m0, NF, k0, tid);
                load_tile64(sa + 2 * TILE_B, Gh, n0, NF, k0, tid);
                load_tile64(sa + 3 * TILE_B, Gl, n0, NF, k0, tid);
                cp_commit();
                asm volatile("cp.async.wait_group 2;\n" ::: "memory");
            } else if (k + 1 < 32) {
                asm volatile("cp.async.wait_group 1;\n" ::: "memory");
            } else {
                asm volatile("cp.async.wait_group 0;\n" ::: "memory");
            }
            __syncthreads();
            asm volatile("fence.proxy.async.shared::cta;" ::: "memory");

            if (wid == 0 && elect_one()) {
                uint32_t sc = sb + SM_BUF + s * STG_B;
                uint64_t ah = mkdesc64(sc);
                uint64_t al = mkdesc64(sc + TILE_B);
                uint64_t bh = mkdesc64(sc + 2 * TILE_B);
                uint64_t bl = mkdesc64(sc + 3 * TILE_B);
                bool first = (k == 0);
#pragma unroll
                for (int ks = 0; ks < 2; ks++)
                    mma_bf16_ss(tbase, ah + ks * 2, bh + ks * 2, IDESC, !(first && ks == 0));
#pragma unroll
                for (int ks = 0; ks < 2; ks++)
                    mma_bf16_ss(tbase, ah + ks * 2, bl + ks * 2, IDESC, true);
#pragma unroll
                for (int ks = 0; ks < 2; ks++)
                    mma_bf16_ss(tbase, al + ks * 2, bh + ks * 2, IDESC, true);
                tc_commit(sb + 8 + s * 8);
            }
            nCommit[s]++;
        }

        // chunk 31 uses stage 31%3 = 1; in-order completion => all MMAs done
        mbar_wait(sb + 8 + 1 * 8, (nCommit[1] - 1) & 1);
        asm volatile("tcgen05.fence::after_thread_sync;" ::: "memory");

        // AdamW epilogue (R10-proven)
        const int sub = wid & 3;
        const int wg = wid >> 2;
        const int lane = tid & 31;
        const int row = m0 + sub * 32 + lane;

#pragma unroll
        for (int qi = 0; qi < 2; qi++) {
            const int q = wg * 2 + qi;
            uint32_t d[32];
            ldtm32(d, tbase + q * 32);
            asm volatile("tcgen05.wait::ld.sync.aligned;" ::: "memory");
            const int cbase = n0 + q * 32;
            const size_t base = (size_t)row * NF + cbase;
#pragma unroll
            for (int h2 = 0; h2 < 2; h2++) {
                float4 uo[4], mo[4], vo[4], ex[4];
#pragma unroll
                for (int j = 0; j < 4; j++) {
                    int jj = h2 * 4 + j;
                    uo[j] = *(const float4*)(g_u + base + jj * 4);
                    mo[j] = *(const float4*)(g_m + base + jj * 4);
                    vo[j] = *(const float4*)(g_v + base + jj * 4);
                    ex[j] = *(const float4*)(g_excite + base + jj * 4);
                }
#pragma unroll
                for (int j = 0; j < 4; j++) {
                    int jj = h2 * 4 + j;
                    float uoa[4] = {uo[j].x, uo[j].y, uo[j].z, uo[j].w};
                    float moa[4] = {mo[j].x, mo[j].y, mo[j].z, mo[j].w};
                    float voa[4] = {vo[j].x, vo[j].y, vo[j].z, vo[j].w};
                    float exa[4] = {ex[j].x, ex[j].y, ex[j].z, ex[j].w};
                    float4 mn4, vn4, un4;
                    float* mnp = &mn4.x; float* vnp = &vn4.x; float* unp = &un4.x;
                    float ac[4];
#pragma unroll
                    for (int c = 0; c < 4; c++) {
                        float sv = __uint_as_float(d[jj * 4 + c]);
                        float g = uoa[c] - exa[c] + sv;
                        float mn = 0.9f * moa[c] + 0.1f * g;
                        float vn = 0.999f * voa[c] + 0.001f * g * g;
                        float u2 = uoa[c] * (1.0f - LR * WD);
                        u2 -= LR * (mn * c1) / (sqrtf(vn * c2) + EPS);
                        mnp[c] = mn; vnp[c] = vn; unp[c] = u2;
                        ac[c] = fmaxf(u2 - SHRINK, 0.0f);
                    }
                    *(float4*)(g_u + base + jj * 4) = un4;
                    *(float4*)(g_m + base + jj * 4) = mn4;
                    *(float4*)(g_v + base + jj * 4) = vn4;
                    __nv_bfloat162 hh0, hh1, ll0, ll1;
                    hh0.x = __float2bfloat16(ac[0]); hh0.y = __float2bfloat16(ac[1]);
                    hh1.x = __float2bfloat16(ac[2]); hh1.y = __float2bfloat16(ac[3]);
                    ll0.x = __float2bfloat16(ac[0] - __bfloat162float(hh0.x));
                    ll0.y = __float2bfloat16(ac[1] - __bfloat162float(hh0.y));
                    ll1.x = __float2bfloat16(ac[2] - __bfloat162float(hh1.x));
                    ll1.y = __float2bfloat16(ac[3] - __bfloat162float(hh1.y));
                    *(__nv_bfloat162*)(Wh + base + jj * 4) = hh0;
                    *(__nv_bfloat162*)(Wh + base + jj * 4 + 2) = hh1;
                    *(__nv_bfloat162*)(Wl + base + jj * 4) = ll0;
                    *(__nv_bfloat162*)(Wl + base + jj * 4 + 2) = ll1;
                    if (last) {
                        float4 a4; a4.x = ac[0]; a4.y = ac[1]; a4.z = ac[2]; a4.w = ac[3];
                        *(float4*)(actOut + base + jj * 4) = a4;
                    }
                }
            }
        }
        asm volatile("tcgen05.fence::before_thread_sync;" ::: "memory");

        if (!last) {
            // global grid barrier (R10-proven)
            __threadfence();
            __syncthreads();
            if (tid == 0) {
                atomicAdd(&g_bar, 1u);
                const unsigned target = (unsigned)(t - 3) * nCta;
                unsigned v;
                do {
                    asm volatile("ld.global.acquire.gpu.b32 %0, [%1];"
                                 : "=r"(v) : "l"(&g_bar));
                    if (v >= target) break;
                    __nanosleep(128);
                } while (true);
            }
            __syncthreads();
        }
    }

    __syncthreads();
    if (wid == 0)
        asm volatile("tcgen05.dealloc.cta_group::1.sync.aligned.b32 %0, %1;"
                     :: "r"(tbase), "r"((uint32_t)BN));
#else
    (void)Gh; (void)Gl; (void)ahb; (void)alb; (void)actOut;
#endif
}

// ---------------- fused elementwise AdamW steps 1..3 ------------------------
// With u0=m0=v0=0: |u1| < 0.1, |u2| < 0.2005 < SHRINK -> act1 = act2 = 0
// exactly, so S=0 for steps 1..3; the whole prefix is pointwise.
__global__ void k_step_ew3(float c11, float c21, float c12, float c22,
                           float c13, float c23,
                           __nv_bfloat16* __restrict__ awh,
                           __nv_bfloat16* __restrict__ awl) {
    size_t i4 = (size_t)blockIdx.x * blockDim.x + threadIdx.x;
    if (i4 == 0) g_bar = 0u;   // reset grid-barrier counter every call
    if (i4 >= (size_t)NB * NF / 4) return;
    float4 ex4 = ((const float4*)g_excite)[i4];
    float exa[4] = {ex4.x, ex4.y, ex4.z, ex4.w};
    float4 un4, mn4, vn4;
    float* unp = &un4.x; float* mnp = &mn4.x; float* vnp = &vn4.x;
    size_t b = i4 * 4;
#pragma unroll
    for (int c = 0; c < 4; c++) {
        float u = 0.f, m = 0.f, v = 0.f;
        float cc1[3] = {c11, c12, c13};
        float cc2[3] = {c21, c22, c23};
#pragma unroll
        for (int t = 0; t < 3; t++) {
            float g = u - exa[c];
            m = 0.9f * m + 0.1f * g;
            v = 0.999f * v + 0.001f * g * g;
            u = u * (1.0f - LR * WD);
            u -= LR * (m * cc1[t]) / (sqrtf(v * cc2[t]) + EPS);
        }
        unp[c] = u; mnp[c] = m; vnp[c] = v;
        float ac = fmaxf(u - SHRINK, 0.0f);
        __nv_bfloat16 h = __float2bfloat16(ac);
        awh[b + c] = h;
        awl[b + c] = __float2bfloat16(ac - __bfloat162float(h));
    }
    ((float4*)g_u)[i4] = un4;
    ((float4*)g_m)[i4] = mn4;
    ((float4*)g_v)[i4] = vn4;
}

// ---------------- converts ---------------------------------------------------
__global__ void k_conv_img(const float* __restrict__ img) {
    size_t i = (size_t)blockIdx.x * blockDim.x + threadIdx.x;
    if (i < (size_t)NB * NP) {
        float x = img[i];
        __nv_bfloat16 h = __float2bfloat16(x);
        g_imgh[i] = h;
        g_imgl[i] = __float2bfloat16(x - __bfloat162float(h));
    }
}

__global__ void k_conv_phi(const float* __restrict__ f) {
    __shared__ float tile[32][33];
    int c0 = blockIdx.x * 32, p0 = blockIdx.y * 32;
    int tx = threadIdx.x, ty = threadIdx.y;
#pragma unroll
    for (int i = ty; i < 32; i += 8) {
        float x = f[(size_t)(p0 + i) * NF + c0 + tx];
        tile[i][tx] = x;
        __nv_bfloat16 h = __float2bfloat16(x);
        size_t idx = (size_t)(p0 + i) * NF + c0 + tx;
        g_phih[idx] = h;
        g_phil[idx] = __float2bfloat16(x - __bfloat162float(h));
    }
    __syncthreads();
#pragma unroll
    for (int i = ty; i < 32; i += 8) {
        float x = tile[tx][i];
        __nv_bfloat16 h = __float2bfloat16(x);
        size_t idx = (size_t)(c0 + i) * NP + p0 + tx;
        g_phith[idx] = h;
        g_phitl[idx] = __float2bfloat16(x - __bfloat162float(h));
    }
}

// ---------------- launcher ---------------------------------------------------
extern "C" void kernel_launch(void* const* d_in, const int* in_sizes, int n_in,
                              void* d_out, int out_size) {
    const float* images  = (const float*)d_in[0];
    const float* filters = (const float*)d_in[1];
    if (in_sizes[0] == NP * NF && in_sizes[1] == NB * NP) {
        filters = (const float*)d_in[0];
        images  = (const float*)d_in[1];
    }
    float* out = (float*)d_out;

    cudaFuncSetAttribute(mma_gemm<0>, cudaFuncAttributeMaxDynamicSharedMemorySize, SMEM_GEMM);
    cudaFuncSetAttribute(mma_gemm<1>, cudaFuncAttributeMaxDynamicSharedMemorySize, SMEM_GEMM);
    cudaFuncSetAttribute(step_persistent, cudaFuncAttributeMaxDynamicSharedMemorySize, SMEM_GEMM);

    const __nv_bfloat16 *imgh, *imgl, *phih, *phil, *phith, *phitl, *Gh, *Gl;
    __nv_bfloat16 *acth0, *actl0;
    float *excite;
    cudaGetSymbolAddress((void**)&imgh, g_imgh);
    cudaGetSymbolAddress((void**)&imgl, g_imgl);
    cudaGetSymbolAddress((void**)&phih, g_phih);
    cudaGetSymbolAddress((void**)&phil, g_phil);
    cudaGetSymbolAddress((void**)&phith, g_phith);
    cudaGetSymbolAddress((void**)&phitl, g_phitl);
    cudaGetSymbolAddress((void**)&Gh, g_Gh);
    cudaGetSymbolAddress((void**)&Gl, g_Gl);
    cudaGetSymbolAddress((void**)&acth0, g_acth);
    cudaGetSymbolAddress((void**)&actl0, g_actl);
    cudaGetSymbolAddress((void**)&excite, g_excite);
    __nv_bfloat16* ah[2] = {acth0, acth0 + NBNF};
    __nv_bfloat16* al[2] = {actl0, actl0 + NBNF};
    float* actOut = out + (size_t)NB * NP;   // acts region of d_out

    {
        size_t n = (size_t)NB * NP;
        k_conv_img<<<(unsigned)((n + 255) / 256), 256>>>(images);
    }
    k_conv_phi<<<dim3(NF / 32, NP / 32), dim3(32, 8)>>>(filters);

    // G = Phi^T Phi - I
    {
        GP p{};
        p.Ah = phith; p.Al = phitl; p.Bh = phith; p.Bl = phitl;
        p.ldA = NP; p.ldB = NP; p.kIters = NP / 32;
        mma_gemm<1><<<dim3(NF / BN, NF / 128), NTHR, SMEM_GEMM>>>(p);
    }

    // excite = images @ Phi
    {
        GP p{};
        p.Ah = imgh; p.Al = imgl; p.Bh = phith; p.Bl = phitl;
        p.ldA = NP; p.ldB = NP; p.kIters = NP / 32;
        p.outF = excite; p.ldc = NF;
        mma_gemm<0><<<dim3(NF / BN, NB / 128), NTHR, SMEM_GEMM>>>(p);
    }

    // steps 1..3 fused elementwise (act provably 0); also resets g_bar
    double b1t = 1.0, b2t = 1.0;
    float c1s[3], c2s[3];
    for (int t = 0; t < 3; t++) {
        b1t *= 0.9; b2t *= 0.999;
        c1s[t] = (float)(1.0 / (1.0 - b1t));
        c2s[t] = (float)(1.0 / (1.0 - b2t));
    }
    {
        unsigned ewg = (unsigned)(((size_t)NB * NF / 4 + 255) / 256);
        k_step_ew3<<<ewg, 256>>>(c1s[0], c2s[0], c1s[1], c2s[1], c1s[2], c2s[2],
                                 ah[1], al[1]);   // t=3 -> buf 1
    }

    // steps 4..50 in ONE persistent launch; final acts -> d_out directly
    step_persistent<<<dim3(NF / BN, NB / 128), NTHR, SMEM_GEMM>>>(
        Gh, Gl, acth0, actl0, actOut);

    // recon = act @ Phi^T -> d_out  (act final in buf 0 since STEPS even)
    {
        GP p{};
        p.Ah = ah[STEPS & 1]; p.Al = al[STEPS & 1];
        p.Bh = phih; p.Bl = phil;
        p.ldA = NF; p.ldB = NF; p.kIters = NF / 32;
        p.outF = out; p.ldc = NP;
        mma_gemm<0><<<dim3(NP / BN, NB / 128), NTHR, SMEM_GEMM>>>(p);
    }
}

// round 13
// speedup vs baseline: 1.0745x; 1.0745x over previous
#include <cuda_runtime.h>
#include <cuda_bf16.h>
#include <stdint.h>
#include <math.h>

#define NB 4096
#define NP 4096
#define NF 1024
#define SHRINK 0.25f
#define LR 0.1f
#define EPS 1e-8f
#define WD 1e-2f
#define STEPS 50

#if defined(__CUDA_ARCH_FEAT_SM103_ALL) || defined(__CUDA_ARCH_FEAT_SM100_ALL) || \
    defined(__CUDA_ARCH_FEAT_SM101_ALL) || defined(__CUDA_ARCH_FEAT_SM120_ALL)
#define TC_OK 1
#else
#define TC_OK 0
#endif

#define NTHR 256
#define BN 128

static const size_t NBNF = (size_t)NB * NF;

// ---------------- persistent device state ----------------------------------
__device__ float g_u[(size_t)NB * NF];
__device__ float g_m[(size_t)NB * NF];
__device__ float g_v[(size_t)NB * NF];
__device__ float g_excite[(size_t)NB * NF];
__device__ __nv_bfloat16 g_acth[2][(size_t)NB * NF];
__device__ __nv_bfloat16 g_actl[2][(size_t)NB * NF];
__device__ __nv_bfloat16 g_imgh[(size_t)NB * NP];
__device__ __nv_bfloat16 g_imgl[(size_t)NB * NP];
__device__ __nv_bfloat16 g_phih[(size_t)NP * NF];
__device__ __nv_bfloat16 g_phil[(size_t)NP * NF];
__device__ __nv_bfloat16 g_phith[(size_t)NF * NP];
__device__ __nv_bfloat16 g_phitl[(size_t)NF * NP];
__device__ __nv_bfloat16 g_Gh[(size_t)NF * NF];
__device__ __nv_bfloat16 g_Gl[(size_t)NF * NF];
__device__ unsigned int g_bar;   // grid-barrier counter (reset each call)

// ---------------- PTX helpers ----------------------------------------------
__device__ __forceinline__ uint32_t smem_u32(const void* p) {
    uint32_t a;
    asm("{ .reg .u64 t; cvta.to.shared.u64 t, %1; cvt.u32.u64 %0, t; }"
        : "=r"(a) : "l"(p));
    return a;
}
__device__ __forceinline__ uint32_t elect_one() {
    uint32_t p;
    asm volatile("{\n\t.reg .pred p;\n\telect.sync _|p, 0xFFFFFFFF;\n\t"
                 "selp.b32 %0, 1, 0, p;\n\t}" : "=r"(p));
    return p;
}
__device__ __forceinline__ void cp_async16(uint32_t dst, const void* src) {
    asm volatile("cp.async.cg.shared.global [%0], [%1], 16;\n" :: "r"(dst), "l"(src));
}
__device__ __forceinline__ void cp_commit() {
    asm volatile("cp.async.commit_group;\n" ::: "memory");
}
// SW64 descriptor: layout=4, version=1 (Blackwell), SBO=32 (512B atom), LBO=1
__device__ __forceinline__ uint64_t mkdesc64(uint32_t addr) {
    return ((uint64_t)4 << 61) | ((uint64_t)1 << 46) | ((uint64_t)32 << 32) |
           ((uint64_t)1 << 16) | ((uint64_t)(addr >> 4) & 0x3FFF);
}
__device__ __forceinline__ void mma_bf16_ss(uint32_t d_tmem, uint64_t a_desc,
                                            uint64_t b_desc, uint32_t idesc, bool acc) {
    uint32_t en = acc ? 1u : 0u;
    asm volatile(
        "{\n\t.reg .pred p;\n\tsetp.ne.u32 p, %5, 0;\n\t"
        "tcgen05.mma.cta_group::1.kind::f16 [%0], %1, %2, %3, {%4,%4,%4,%4}, p;\n\t}"
        :: "r"(d_tmem), "l"(a_desc), "l"(b_desc), "r"(idesc), "r"(0u), "r"(en)
        : "memory");
}
__device__ __forceinline__ void mbar_init(uint32_t a, uint32_t cnt) {
    asm volatile("mbarrier.init.shared.b64 [%0], %1;" :: "r"(a), "r"(cnt) : "memory");
}
__device__ __forceinline__ void mbar_wait(uint32_t a, uint32_t phase) {
    asm volatile(
        "{\n\t.reg .pred P;\n\tLW%=:\n\t"
        "mbarrier.try_wait.parity.shared.b64 P, [%0], %1;\n\t"
        "@!P bra LW%=;\n\t}" :: "r"(a), "r"(phase) : "memory");
}
__device__ __forceinline__ void tc_commit(uint32_t mbar) {
    asm volatile(
        "tcgen05.commit.cta_group::1.mbarrier::arrive::one.shared::cluster.b64 [%0];"
        :: "r"(mbar) : "memory");
}
__device__ __forceinline__ void ldtm32(uint32_t (&r)[32], uint32_t a) {
    asm volatile(
        "tcgen05.ld.sync.aligned.32x32b.x32.b32 "
        "{%0,%1,%2,%3,%4,%5,%6,%7,%8,%9,%10,%11,%12,%13,%14,%15,"
        "%16,%17,%18,%19,%20,%21,%22,%23,%24,%25,%26,%27,%28,%29,%30,%31}, [%32];"
        : "=r"(r[0]), "=r"(r[1]), "=r"(r[2]), "=r"(r[3]), "=r"(r[4]), "=r"(r[5]),
          "=r"(r[6]), "=r"(r[7]), "=r"(r[8]), "=r"(r[9]), "=r"(r[10]), "=r"(r[11]),
          "=r"(r[12]), "=r"(r[13]), "=r"(r[14]), "=r"(r[15]), "=r"(r[16]),
          "=r"(r[17]), "=r"(r[18]), "=r"(r[19]), "=r"(r[20]), "=r"(r[21]),
          "=r"(r[22]), "=r"(r[23]), "=r"(r[24]), "=r"(r[25]), "=r"(r[26]),
          "=r"(r[27]), "=r"(r[28]), "=r"(r[29]), "=r"(r[30]), "=r"(r[31])
        : "r"(a));
}

// smem: [0..4) tmem ptr, [8..32) mbars, [1024..) stages
#define SM_BUF 1024
#define TILE_B 8192                       // 128 rows x 64B (SW64)
#define STG_B (4 * TILE_B)                // Ah, Al, Bh, Bl
#define SMEM_STANDALONE (SM_BUF + 3 * STG_B)   // 99328 (3-stage, R8-proven)
#define SMEM_PERSIST    (SM_BUF + 2 * STG_B)   // 66560 (2-stage, R10-proven)
// idesc: F32 acc, BF16 a/b, N=128, M=128
#define IDESC 0x8200490u

// Load 128-row x 32-col bf16 tile (64B/row), SW64 swizzled. NTHR threads.
__device__ __forceinline__ void load_tile64(uint32_t dst, const __nv_bfloat16* src,
                                            int row0, int ld, int k0, int tid) {
    const char* base = (const char*)(src + (size_t)row0 * ld + k0);
    const size_t ldb = (size_t)ld * 2;
#pragma unroll
    for (int i = 0; i < 512 / NTHR; i++) {
        int cg = tid + i * NTHR;            // 0..511
        int r = cg >> 2, c = cg & 3;        // 128 rows x 4 16B blocks
        uint32_t off = (uint32_t)(r * 64 + c * 16);
        uint32_t sw = off ^ ((off >> 3) & 0x30);
        cp_async16(dst + sw, base + (size_t)r * ldb + c * 16);
    }
}

struct GP {
    const __nv_bfloat16 *Ah, *Al, *Bh, *Bl;
    int ldA, ldB, kIters;
    float* outF; int ldc;             // EPI 0
};

// ---------------------------------------------------------------------------
// Standalone GEMM (R8-proven): 3-stage pipeline, full bf16 split (3 MMAs).
// EPI: 0 = fp32 store, 1 = G (-I, bf16 split out)
// ---------------------------------------------------------------------------
template <int EPI>
__global__ __launch_bounds__(NTHR) void mma_gemm(GP P) {
#if TC_OK
    extern __shared__ char smem[];
    const uint32_t sb = smem_u32(smem);
    const int tid = threadIdx.x;
    const int wid = tid >> 5;
    const int m0 = blockIdx.y * 128, n0 = blockIdx.x * BN;
    const int K = P.kIters;

    if (wid == 0) {
        asm volatile("tcgen05.alloc.cta_group::1.sync.aligned.shared::cta.b32 [%0], %1;"
                     :: "r"(sb + 0), "r"((uint32_t)BN) : "memory");
        asm volatile("tcgen05.relinquish_alloc_permit.cta_group::1.sync.aligned;");
    }
    if (tid < 3) mbar_init(sb + 8 + tid * 8, 1);
    __syncthreads();
    uint32_t tbase;
    asm volatile("ld.shared.b32 %0, [%1];" : "=r"(tbase) : "r"(sb + 0));

#pragma unroll
    for (int c = 0; c < 2; c++) {
        uint32_t s = sb + SM_BUF + c * STG_B;
        int k0 = c * 32;
        load_tile64(s,              P.Ah, m0, P.ldA, k0, tid);
        load_tile64(s + TILE_B,     P.Al, m0, P.ldA, k0, tid);
        load_tile64(s + 2 * TILE_B, P.Bh, n0, P.ldB, k0, tid);
        load_tile64(s + 3 * TILE_B, P.Bl, n0, P.ldB, k0, tid);
        cp_commit();
    }

    for (int k = 0; k < K; k++) {
        if (k + 2 < K) {
            if (k >= 1) mbar_wait(sb + 8 + ((k + 2) % 3) * 8, ((k - 1) / 3) & 1);
            uint32_t s = sb + SM_BUF + ((k + 2) % 3) * STG_B;
            int k0 = (k + 2) * 32;
            load_tile64(s,              P.Ah, m0, P.ldA, k0, tid);
            load_tile64(s + TILE_B,     P.Al, m0, P.ldA, k0, tid);
            load_tile64(s + 2 * TILE_B, P.Bh, n0, P.ldB, k0, tid);
            load_tile64(s + 3 * TILE_B, P.Bl, n0, P.ldB, k0, tid);
            cp_commit();
            asm volatile("cp.async.wait_group 2;\n" ::: "memory");
        } else if (k + 1 < K) {
            asm volatile("cp.async.wait_group 1;\n" ::: "memory");
        } else {
            asm volatile("cp.async.wait_group 0;\n" ::: "memory");
        }
        __syncthreads();
        asm volatile("fence.proxy.async.shared::cta;" ::: "memory");

        if (wid == 0 && elect_one()) {
            uint32_t sc = sb + SM_BUF + (k % 3) * STG_B;
            uint64_t ah = mkdesc64(sc);
            uint64_t al = mkdesc64(sc + TILE_B);
            uint64_t bh = mkdesc64(sc + 2 * TILE_B);
            uint64_t bl = mkdesc64(sc + 3 * TILE_B);
            bool first = (k == 0);
#pragma unroll
            for (int ks = 0; ks < 2; ks++)
                mma_bf16_ss(tbase, ah + ks * 2, bh + ks * 2, IDESC, !(first && ks == 0));
#pragma unroll
            for (int ks = 0; ks < 2; ks++)
                mma_bf16_ss(tbase, ah + ks * 2, bl + ks * 2, IDESC, true);
#pragma unroll
            for (int ks = 0; ks < 2; ks++)
                mma_bf16_ss(tbase, al + ks * 2, bh + ks * 2, IDESC, true);
            tc_commit(sb + 8 + (k % 3) * 8);
        }
    }

    mbar_wait(sb + 8 + ((K - 1) % 3) * 8, ((K - 1) / 3) & 1);
    asm volatile("tcgen05.fence::after_thread_sync;" ::: "memory");

    const int sub = wid & 3;
    const int wg = wid >> 2;
    const int lane = tid & 31;
    const int row = m0 + sub * 32 + lane;

#pragma unroll
    for (int qi = 0; qi < 2; qi++) {
        const int q = wg * 2 + qi;
        uint32_t d[32];
        ldtm32(d, tbase + q * 32);
        asm volatile("tcgen05.wait::ld.sync.aligned;" ::: "memory");
        const int cbase = n0 + q * 32;

        if constexpr (EPI == 0) {
            float4* o = (float4*)(P.outF + (size_t)row * P.ldc + cbase);
#pragma unroll
            for (int jj = 0; jj < 8; jj++) {
                float4 v;
                v.x = __uint_as_float(d[jj * 4 + 0]);
                v.y = __uint_as_float(d[jj * 4 + 1]);
                v.z = __uint_as_float(d[jj * 4 + 2]);
                v.w = __uint_as_float(d[jj * 4 + 3]);
                o[jj] = v;
            }
        } else {
#pragma unroll
            for (int j = 0; j < 32; j++) {
                float val = __uint_as_float(d[j]);
                if (row == cbase + j) val -= 1.0f;
                __nv_bfloat16 h = __float2bfloat16(val);
                __nv_bfloat16 l = __float2bfloat16(val - __bfloat162float(h));
                size_t idx = (size_t)row * NF + cbase + j;
                g_Gh[idx] = h;
                g_Gl[idx] = l;
            }
        }
    }

    asm volatile("tcgen05.fence::before_thread_sync;" ::: "memory");
    __syncthreads();
    if (wid == 0)
        asm volatile("tcgen05.dealloc.cta_group::1.sync.aligned.b32 %0, %1;"
                     :: "r"(tbase), "r"((uint32_t)BN));
#else
    (void)P;
#endif
}

// ---------------------------------------------------------------------------
// Persistent step kernel (steps 4..50, one launch) — R10-proven config:
// 2-stage pipeline (66.5KB smem -> 2 CTAs/SM with ~95KB L1D left for state),
// global grid barrier between steps. Final acts written directly to d_out.
// ---------------------------------------------------------------------------
__global__ __launch_bounds__(NTHR, 2) void step_persistent(
    const __nv_bfloat16* __restrict__ Gh, const __nv_bfloat16* __restrict__ Gl,
    __nv_bfloat16* __restrict__ ahb, __nv_bfloat16* __restrict__ alb,
    float* __restrict__ actOut)
{
#if TC_OK
    extern __shared__ char smem[];
    const uint32_t sb = smem_u32(smem);
    const int tid = threadIdx.x;
    const int wid = tid >> 5;
    const int m0 = blockIdx.y * 128, n0 = blockIdx.x * BN;
    const size_t NN = (size_t)NB * NF;
    const unsigned nCta = gridDim.x * gridDim.y;

    if (wid == 0) {
        asm volatile("tcgen05.alloc.cta_group::1.sync.aligned.shared::cta.b32 [%0], %1;"
                     :: "r"(sb + 0), "r"((uint32_t)BN) : "memory");
        asm volatile("tcgen05.relinquish_alloc_permit.cta_group::1.sync.aligned;");
    }
    if (tid < 2) mbar_init(sb + 8 + tid * 8, 1);
    __syncthreads();
    uint32_t tbase;
    asm volatile("ld.shared.b32 %0, [%1];" : "=r"(tbase) : "r"(sb + 0));

    unsigned nCommit[2] = {0u, 0u};   // commits issued per stage (uniform)

    for (int t = 4; t <= STEPS; t++) {
        const __nv_bfloat16* Ah = ahb + (((t - 1) & 1) ? NN : 0);
        const __nv_bfloat16* Al = alb + (((t - 1) & 1) ? NN : 0);
        __nv_bfloat16* Wh = ahb + ((t & 1) ? NN : 0);
        __nv_bfloat16* Wl = alb + ((t & 1) ? NN : 0);
        const float c1 = 1.0f / (1.0f - powf(0.9f,   (float)t));
        const float c2 = 1.0f / (1.0f - powf(0.999f, (float)t));
        const bool last = (t == STEPS);

        // prologue: chunk 0 -> stage 0 (previous step's MMAs all complete)
        {
            uint32_t s = sb + SM_BUF;
            load_tile64(s,              Ah, m0, NF, 0, tid);
            load_tile64(s + TILE_B,     Al, m0, NF, 0, tid);
            load_tile64(s + 2 * TILE_B, Gh, n0, NF, 0, tid);
            load_tile64(s + 3 * TILE_B, Gl, n0, NF, 0, tid);
            cp_commit();
        }

        for (int k = 0; k < 32; k++) {
            const int s = k & 1;
            if (k + 1 < 32) {
                const int s2 = (k + 1) & 1;
                if (nCommit[s2] > 0)
                    mbar_wait(sb + 8 + s2 * 8, (nCommit[s2] - 1) & 1);
                uint32_t sa = sb + SM_BUF + s2 * STG_B;
                int k0 = (k + 1) * 32;
                load_tile64(sa,              Ah, m0, NF, k0, tid);
                load_tile64(sa + TILE_B,     Al, m0, NF, k0, tid);
                load_tile64(sa + 2 * TILE_B, Gh, n0, NF, k0, tid);
                load_tile64(sa + 3 * TILE_B, Gl, n0, NF, k0, tid);
                cp_commit();
                asm volatile("cp.async.wait_group 1;\n" ::: "memory");
            } else {
                asm volatile("cp.async.wait_group 0;\n" ::: "memory");
            }
            __syncthreads();
            asm volatile("fence.proxy.async.shared::cta;" ::: "memory");

            if (wid == 0 && elect_one()) {
                uint32_t sc = sb + SM_BUF + s * STG_B;
                uint64_t ah = mkdesc64(sc);
                uint64_t al = mkdesc64(sc + TILE_B);
                uint64_t bh = mkdesc64(sc + 2 * TILE_B);
                uint64_t bl = mkdesc64(sc + 3 * TILE_B);
                bool first = (k == 0);
#pragma unroll
                for (int ks = 0; ks < 2; ks++)
                    mma_bf16_ss(tbase, ah + ks * 2, bh + ks * 2, IDESC, !(first && ks == 0));
#pragma unroll
                for (int ks = 0; ks < 2; ks++)
                    mma_bf16_ss(tbase, ah + ks * 2, bl + ks * 2, IDESC, true);
#pragma unroll
                for (int ks = 0; ks < 2; ks++)
                    mma_bf16_ss(tbase, al + ks * 2, bh + ks * 2, IDESC, true);
                tc_commit(sb + 8 + s * 8);
            }
            nCommit[s]++;
        }

        // wait for chunk 31 commit (stage 1); in-order => all MMAs done
        mbar_wait(sb + 8 + 8, (nCommit[1] - 1) & 1);
        asm volatile("tcgen05.fence::after_thread_sync;" ::: "memory");

        // AdamW epilogue
        const int sub = wid & 3;
        const int wg = wid >> 2;
        const int lane = tid & 31;
        const int row = m0 + sub * 32 + lane;

#pragma unroll
        for (int qi = 0; qi < 2; qi++) {
            const int q = wg * 2 + qi;
            uint32_t d[32];
            ldtm32(d, tbase + q * 32);
            asm volatile("tcgen05.wait::ld.sync.aligned;" ::: "memory");
            const int cbase = n0 + q * 32;
            const size_t base = (size_t)row * NF + cbase;
#pragma unroll
            for (int h2 = 0; h2 < 2; h2++) {
                float4 uo[4], mo[4], vo[4], ex[4];
#pragma unroll
                for (int j = 0; j < 4; j++) {
                    int jj = h2 * 4 + j;
                    uo[j] = *(const float4*)(g_u + base + jj * 4);
                    mo[j] = *(const float4*)(g_m + base + jj * 4);
                    vo[j] = *(const float4*)(g_v + base + jj * 4);
                    ex[j] = *(const float4*)(g_excite + base + jj * 4);
                }
#pragma unroll
                for (int j = 0; j < 4; j++) {
                    int jj = h2 * 4 + j;
                    float uoa[4] = {uo[j].x, uo[j].y, uo[j].z, uo[j].w};
                    float moa[4] = {mo[j].x, mo[j].y, mo[j].z, mo[j].w};
                    float voa[4] = {vo[j].x, vo[j].y, vo[j].z, vo[j].w};
                    float exa[4] = {ex[j].x, ex[j].y, ex[j].z, ex[j].w};
                    float4 mn4, vn4, un4;
                    float* mnp = &mn4.x; float* vnp = &vn4.x; float* unp = &un4.x;
                    float ac[4];
#pragma unroll
                    for (int c = 0; c < 4; c++) {
                        float sv = __uint_as_float(d[jj * 4 + c]);
                        float g = uoa[c] - exa[c] + sv;
                        float mn = 0.9f * moa[c] + 0.1f * g;
                        float vn = 0.999f * voa[c] + 0.001f * g * g;
                        float u2 = uoa[c] * (1.0f - LR * WD);
                        u2 -= LR * (mn * c1) / (sqrtf(vn * c2) + EPS);
                        mnp[c] = mn; vnp[c] = vn; unp[c] = u2;
                        ac[c] = fmaxf(u2 - SHRINK, 0.0f);
                    }
                    *(float4*)(g_u + base + jj * 4) = un4;
                    *(float4*)(g_m + base + jj * 4) = mn4;
                    *(float4*)(g_v + base + jj * 4) = vn4;
                    __nv_bfloat162 hh0, hh1, ll0, ll1;
                    hh0.x = __float2bfloat16(ac[0]); hh0.y = __float2bfloat16(ac[1]);
                    hh1.x = __float2bfloat16(ac[2]); hh1.y = __float2bfloat16(ac[3]);
                    ll0.x = __float2bfloat16(ac[0] - __bfloat162float(hh0.x));
                    ll0.y = __float2bfloat16(ac[1] - __bfloat162float(hh0.y));
                    ll1.x = __float2bfloat16(ac[2] - __bfloat162float(hh1.x));
                    ll1.y = __float2bfloat16(ac[3] - __bfloat162float(hh1.y));
                    *(__nv_bfloat162*)(Wh + base + jj * 4) = hh0;
                    *(__nv_bfloat162*)(Wh + base + jj * 4 + 2) = hh1;
                    *(__nv_bfloat162*)(Wl + base + jj * 4) = ll0;
                    *(__nv_bfloat162*)(Wl + base + jj * 4 + 2) = ll1;
                    if (last) {
                        float4 a4; a4.x = ac[0]; a4.y = ac[1]; a4.z = ac[2]; a4.w = ac[3];
                        *(float4*)(actOut + base + jj * 4) = a4;
                    }
                }
            }
        }
        asm volatile("tcgen05.fence::before_thread_sync;" ::: "memory");

        if (!last) {
            // global grid barrier: publish act writes, arrive, spin
            __threadfence();
            __syncthreads();
            if (tid == 0) {
                atomicAdd(&g_bar, 1u);
                const unsigned target = (unsigned)(t - 3) * nCta;
                unsigned v;
                do {
                    asm volatile("ld.global.acquire.gpu.b32 %0, [%1];"
                                 : "=r"(v) : "l"(&g_bar));
                    if (v >= target) break;
                    __nanosleep(128);
                } while (true);
            }
            __syncthreads();
        }
    }

    __syncthreads();
    if (wid == 0)
        asm volatile("tcgen05.dealloc.cta_group::1.sync.aligned.b32 %0, %1;"
                     :: "r"(tbase), "r"((uint32_t)BN));
#else
    (void)Gh; (void)Gl; (void)ahb; (void)alb; (void)actOut;
#endif
}

// ---------------- fused elementwise AdamW steps 1..3 ------------------------
// With u0=m0=v0=0: |u1| < 0.1, |u2| < 0.2005 < SHRINK -> act1 = act2 = 0
// exactly, so S=0 for steps 1..3; the whole prefix is pointwise.
__global__ void k_step_ew3(float c11, float c21, float c12, float c22,
                           float c13, float c23,
                           __nv_bfloat16* __restrict__ awh,
                           __nv_bfloat16* __restrict__ awl) {
    size_t i4 = (size_t)blockIdx.x * blockDim.x + threadIdx.x;
    if (i4 == 0) g_bar = 0u;   // reset grid-barrier counter every call
    if (i4 >= (size_t)NB * NF / 4) return;
    float4 ex4 = ((const float4*)g_excite)[i4];
    float exa[4] = {ex4.x, ex4.y, ex4.z, ex4.w};
    float4 un4, mn4, vn4;
    float* unp = &un4.x; float* mnp = &mn4.x; float* vnp = &vn4.x;
    size_t b = i4 * 4;
#pragma unroll
    for (int c = 0; c < 4; c++) {
        float u = 0.f, m = 0.f, v = 0.f;
        float cc1[3] = {c11, c12, c13};
        float cc2[3] = {c21, c22, c23};
#pragma unroll
        for (int t = 0; t < 3; t++) {
            float g = u - exa[c];
            m = 0.9f * m + 0.1f * g;
            v = 0.999f * v + 0.001f * g * g;
            u = u * (1.0f - LR * WD);
            u -= LR * (m * cc1[t]) / (sqrtf(v * cc2[t]) + EPS);
        }
        unp[c] = u; mnp[c] = m; vnp[c] = v;
        float ac = fmaxf(u - SHRINK, 0.0f);
        __nv_bfloat16 h = __float2bfloat16(ac);
        awh[b + c] = h;
        awl[b + c] = __float2bfloat16(ac - __bfloat162float(h));
    }
    ((float4*)g_u)[i4] = un4;
    ((float4*)g_m)[i4] = mn4;
    ((float4*)g_v)[i4] = vn4;
}

// ---------------- converts ---------------------------------------------------
__global__ void k_conv_img(const float* __restrict__ img) {
    size_t i = (size_t)blockIdx.x * blockDim.x + threadIdx.x;
    if (i < (size_t)NB * NP) {
        float x = img[i];
        __nv_bfloat16 h = __float2bfloat16(x);
        g_imgh[i] = h;
        g_imgl[i] = __float2bfloat16(x - __bfloat162float(h));
    }
}

__global__ void k_conv_phi(const float* __restrict__ f) {
    __shared__ float tile[32][33];
    int c0 = blockIdx.x * 32, p0 = blockIdx.y * 32;
    int tx = threadIdx.x, ty = threadIdx.y;
#pragma unroll
    for (int i = ty; i < 32; i += 8) {
        float x = f[(size_t)(p0 + i) * NF + c0 + tx];
        tile[i][tx] = x;
        __nv_bfloat16 h = __float2bfloat16(x);
        size_t idx = (size_t)(p0 + i) * NF + c0 + tx;
        g_phih[idx] = h;
        g_phil[idx] = __float2bfloat16(x - __bfloat162float(h));
    }
    __syncthreads();
#pragma unroll
    for (int i = ty; i < 32; i += 8) {
        float x = tile[tx][i];
        __nv_bfloat16 h = __float2bfloat16(x);
        size_t idx = (size_t)(c0 + i) * NP + p0 + tx;
        g_phith[idx] = h;
        g_phitl[idx] = __float2bfloat16(x - __bfloat162float(h));
    }
}

// ---------------- launcher ---------------------------------------------------
extern "C" void kernel_launch(void* const* d_in, const int* in_sizes, int n_in,
                              void* d_out, int out_size) {
    const float* images  = (const float*)d_in[0];
    const float* filters = (const float*)d_in[1];
    if (in_sizes[0] == NP * NF && in_sizes[1] == NB * NP) {
        filters = (const float*)d_in[0];
        images  = (const float*)d_in[1];
    }
    float* out = (float*)d_out;

    cudaFuncSetAttribute(mma_gemm<0>, cudaFuncAttributeMaxDynamicSharedMemorySize, SMEM_STANDALONE);
    cudaFuncSetAttribute(mma_gemm<1>, cudaFuncAttributeMaxDynamicSharedMemorySize, SMEM_STANDALONE);
    cudaFuncSetAttribute(step_persistent, cudaFuncAttributeMaxDynamicSharedMemorySize, SMEM_PERSIST);

    const __nv_bfloat16 *imgh, *imgl, *phih, *phil, *phith, *phitl, *Gh, *Gl;
    __nv_bfloat16 *acth0, *actl0;
    float *excite;
    cudaGetSymbolAddress((void**)&imgh, g_imgh);
    cudaGetSymbolAddress((void**)&imgl, g_imgl);
    cudaGetSymbolAddress((void**)&phih, g_phih);
    cudaGetSymbolAddress((void**)&phil, g_phil);
    cudaGetSymbolAddress((void**)&phith, g_phith);
    cudaGetSymbolAddress((void**)&phitl, g_phitl);
    cudaGetSymbolAddress((void**)&Gh, g_Gh);
    cudaGetSymbolAddress((void**)&Gl, g_Gl);
    cudaGetSymbolAddress((void**)&acth0, g_acth);
    cudaGetSymbolAddress((void**)&actl0, g_actl);
    cudaGetSymbolAddress((void**)&excite, g_excite);
    __nv_bfloat16* ah[2] = {acth0, acth0 + NBNF};
    __nv_bfloat16* al[2] = {actl0, actl0 + NBNF};
    float* actOut = out + (size_t)NB * NP;   // acts region of d_out

    {
        size_t n = (size_t)NB * NP;
        k_conv_img<<<(unsigned)((n + 255) / 256), 256>>>(images);
    }
    k_conv_phi<<<dim3(NF / 32, NP / 32), dim3(32, 8)>>>(filters);

    // G = Phi^T Phi - I
    {
        GP p{};
        p.Ah = phith; p.Al = phitl; p.Bh = phith; p.Bl = phitl;
        p.ldA = NP; p.ldB = NP; p.kIters = NP / 32;
        mma_gemm<1><<<dim3(NF / BN, NF / 128), NTHR, SMEM_STANDALONE>>>(p);
    }

    // excite = images @ Phi
    {
        GP p{};
        p.Ah = imgh; p.Al = imgl; p.Bh = phith; p.Bl = phitl;
        p.ldA = NP; p.ldB = NP; p.kIters = NP / 32;
        p.outF = excite; p.ldc = NF;
        mma_gemm<0><<<dim3(NF / BN, NB / 128), NTHR, SMEM_STANDALONE>>>(p);
    }

    // steps 1..3 fused elementwise (act provably 0); also resets g_bar
    double b1t = 1.0, b2t = 1.0;
    float c1s[3], c2s[3];
    for (int t = 0; t < 3; t++) {
        b1t *= 0.9; b2t *= 0.999;
        c1s[t] = (float)(1.0 / (1.0 - b1t));
        c2s[t] = (float)(1.0 / (1.0 - b2t));
    }
    {
        unsigned ewg = (unsigned)(((size_t)NB * NF / 4 + 255) / 256);
        k_step_ew3<<<ewg, 256>>>(c1s[0], c2s[0], c1s[1], c2s[1], c1s[2], c2s[2],
                                 ah[1], al[1]);   // t=3 -> buf 1
    }

    // steps 4..50 in ONE persistent launch; final acts -> d_out directly
    step_persistent<<<dim3(NF / BN, NB / 128), NTHR, SMEM_PERSIST>>>(
        Gh, Gl, acth0, actl0, actOut);

    // recon = act @ Phi^T -> d_out  (act final in buf 0 since STEPS even)
    {
        GP p{};
        p.Ah = ah[STEPS & 1]; p.Al = al[STEPS & 1];
        p.Bh = phih; p.Bl = phil;
        p.ldA = NF; p.ldB = NF; p.kIters = NF / 32;
        p.outF = out; p.ldc = NP;
        mma_gemm<0><<<dim3(NP / BN, NB / 128), NTHR, SMEM_STANDALONE>>>(p);
    }
}

// round 15
// speedup vs baseline: 1.2967x; 1.2067x over previous
#include <cuda_runtime.h>
#include <cuda_bf16.h>
#include <cuda_fp16.h>
#include <stdint.h>
#include <math.h>

#define NB 4096
#define NP 4096
#define NF 1024
#define SHRINK 0.25f
#define LR 0.1f
#define EPS 1e-8f
#define WD 1e-2f
#define STEPS 50

#if defined(__CUDA_ARCH_FEAT_SM103_ALL) || defined(__CUDA_ARCH_FEAT_SM100_ALL) || \
    defined(__CUDA_ARCH_FEAT_SM101_ALL) || defined(__CUDA_ARCH_FEAT_SM120_ALL)
#define TC_OK 1
#else
#define TC_OK 0
#endif

#define NTHR 256
#define BN 128

static const size_t NBNF = (size_t)NB * NF;

// ---------------- persistent device state ----------------------------------
__device__ float g_u[(size_t)NB * NF];
__device__ float g_m[(size_t)NB * NF];
__device__ float g_v[(size_t)NB * NF];
__device__ float g_excite[(size_t)NB * NF];
__device__ __half g_af16[2][(size_t)NB * NF];        // iteration act, fp16 ping-pong
__device__ __nv_bfloat16 g_acth[(size_t)NB * NF];    // final act bf16 split (recon)
__device__ __nv_bfloat16 g_actl[(size_t)NB * NF];
__device__ __nv_bfloat16 g_imgh[(size_t)NB * NP];
__device__ __nv_bfloat16 g_imgl[(size_t)NB * NP];
__device__ __nv_bfloat16 g_phih[(size_t)NP * NF];
__device__ __nv_bfloat16 g_phil[(size_t)NP * NF];
__device__ __nv_bfloat16 g_phith[(size_t)NF * NP];
__device__ __nv_bfloat16 g_phitl[(size_t)NF * NP];
__device__ __half g_G16h[(size_t)NF * NF];           // G fp16 h/l split (step GEMM)
__device__ __half g_G16l[(size_t)NF * NF];
__device__ unsigned int g_bar;   // grid-barrier counter (reset each call)

// ---------------- PTX helpers ----------------------------------------------
__device__ __forceinline__ uint32_t smem_u32(const void* p) {
    uint32_t a;
    asm("{ .reg .u64 t; cvta.to.shared.u64 t, %1; cvt.u32.u64 %0, t; }"
        : "=r"(a) : "l"(p));
    return a;
}
__device__ __forceinline__ uint32_t elect_one() {
    uint32_t p;
    asm volatile("{\n\t.reg .pred p;\n\telect.sync _|p, 0xFFFFFFFF;\n\t"
                 "selp.b32 %0, 1, 0, p;\n\t}" : "=r"(p));
    return p;
}
__device__ __forceinline__ void cp_async16(uint32_t dst, const void* src) {
    asm volatile("cp.async.cg.shared.global [%0], [%1], 16;\n" :: "r"(dst), "l"(src));
}
__device__ __forceinline__ void cp_commit() {
    asm volatile("cp.async.commit_group;\n" ::: "memory");
}
// SW64 descriptor: layout=4, version=1 (Blackwell), SBO=32 (512B atom), LBO=1
__device__ __forceinline__ uint64_t mkdesc64(uint32_t addr) {
    return ((uint64_t)4 << 61) | ((uint64_t)1 << 46) | ((uint64_t)32 << 32) |
           ((uint64_t)1 << 16) | ((uint64_t)(addr >> 4) & 0x3FFF);
}
__device__ __forceinline__ void mma_f16kind_ss(uint32_t d_tmem, uint64_t a_desc,
                                               uint64_t b_desc, uint32_t idesc, bool acc) {
    uint32_t en = acc ? 1u : 0u;
    asm volatile(
        "{\n\t.reg .pred p;\n\tsetp.ne.u32 p, %5, 0;\n\t"
        "tcgen05.mma.cta_group::1.kind::f16 [%0], %1, %2, %3, {%4,%4,%4,%4}, p;\n\t}"
        :: "r"(d_tmem), "l"(a_desc), "l"(b_desc), "r"(idesc), "r"(0u), "r"(en)
        : "memory");
}
__device__ __forceinline__ void mbar_init(uint32_t a, uint32_t cnt) {
    asm volatile("mbarrier.init.shared.b64 [%0], %1;" :: "r"(a), "r"(cnt) : "memory");
}
__device__ __forceinline__ void mbar_wait(uint32_t a, uint32_t phase) {
    asm volatile(
        "{\n\t.reg .pred P;\n\tLW%=:\n\t"
        "mbarrier.try_wait.parity.shared.b64 P, [%0], %1;\n\t"
        "@!P bra LW%=;\n\t}" :: "r"(a), "r"(phase) : "memory");
}
__device__ __forceinline__ void tc_commit(uint32_t mbar) {
    asm volatile(
        "tcgen05.commit.cta_group::1.mbarrier::arrive::one.shared::cluster.b64 [%0];"
        :: "r"(mbar) : "memory");
}
__device__ __forceinline__ void ldtm32(uint32_t (&r)[32], uint32_t a) {
    asm volatile(
        "tcgen05.ld.sync.aligned.32x32b.x32.b32 "
        "{%0,%1,%2,%3,%4,%5,%6,%7,%8,%9,%10,%11,%12,%13,%14,%15,"
        "%16,%17,%18,%19,%20,%21,%22,%23,%24,%25,%26,%27,%28,%29,%30,%31}, [%32];"
        : "=r"(r[0]), "=r"(r[1]), "=r"(r[2]), "=r"(r[3]), "=r"(r[4]), "=r"(r[5]),
          "=r"(r[6]), "=r"(r[7]), "=r"(r[8]), "=r"(r[9]), "=r"(r[10]), "=r"(r[11]),
          "=r"(r[12]), "=r"(r[13]), "=r"(r[14]), "=r"(r[15]), "=r"(r[16]),
          "=r"(r[17]), "=r"(r[18]), "=r"(r[19]), "=r"(r[20]), "=r"(r[21]),
          "=r"(r[22]), "=r"(r[23]), "=r"(r[24]), "=r"(r[25]), "=r"(r[26]),
          "=r"(r[27]), "=r"(r[28]), "=r"(r[29]), "=r"(r[30]), "=r"(r[31])
        : "r"(a));
}

// smem: [0..4) tmem ptr, [8..32) mbars, [1024..) stages
#define SM_BUF 1024
#define TILE_B 8192                        // 128 rows x 64B (SW64)
#define STG4_B (4 * TILE_B)                // standalone: Ah, Al, Bh, Bl
#define STG3_B (3 * TILE_B)                // step: Af16, G16h, G16l
#define SMEM_STANDALONE (SM_BUF + 3 * STG4_B)   // 99328 (3-stage, R8-proven)
#define SMEM_PERSIST    (SM_BUF + 2 * STG3_B)   // 50176 (2-stage)
// idesc: F32 acc (bit4), atype bits[7:9], btype bits[10:12] (F16=0, BF16=1),
// N/8 << 17, M/16 << 24
#define IDESC_BF16 0x8200490u   // A bf16, B bf16
#define IDESC_F16  0x8200010u   // A f16,  B f16

// Load 128-row x 32-col 2B-elem tile (64B/row), SW64 swizzled. NTHR threads.
__device__ __forceinline__ void load_tile64(uint32_t dst, const void* src,
                                            int row0, int ld, int k0, int tid) {
    const char* base = (const char*)src + ((size_t)row0 * ld + k0) * 2;
    const size_t ldb = (size_t)ld * 2;
#pragma unroll
    for (int i = 0; i < 512 / NTHR; i++) {
        int cg = tid + i * NTHR;            // 0..511
        int r = cg >> 2, c = cg & 3;        // 128 rows x 4 16B blocks
        uint32_t off = (uint32_t)(r * 64 + c * 16);
        uint32_t sw = off ^ ((off >> 3) & 0x30);
        cp_async16(dst + sw, base + (size_t)r * ldb + c * 16);
    }
}

struct GP {
    const __nv_bfloat16 *Ah, *Al, *Bh, *Bl;
    int ldA, ldB, kIters;
    float* outF; int ldc;             // EPI 0
};

// ---------------------------------------------------------------------------
// Standalone GEMM (R8-proven): 3-stage pipeline, full bf16 split (3 MMAs).
// EPI: 0 = fp32 store, 1 = G (-I, fp16 h/l split out for the step kernel)
// ---------------------------------------------------------------------------
template <int EPI>
__global__ __launch_bounds__(NTHR) void mma_gemm(GP P) {
#if TC_OK
    extern __shared__ char smem[];
    const uint32_t sb = smem_u32(smem);
    const int tid = threadIdx.x;
    const int wid = tid >> 5;
    const int m0 = blockIdx.y * 128, n0 = blockIdx.x * BN;
    const int K = P.kIters;

    if (wid == 0) {
        asm volatile("tcgen05.alloc.cta_group::1.sync.aligned.shared::cta.b32 [%0], %1;"
                     :: "r"(sb + 0), "r"((uint32_t)BN) : "memory");
        asm volatile("tcgen05.relinquish_alloc_permit.cta_group::1.sync.aligned;");
    }
    if (tid < 3) mbar_init(sb + 8 + tid * 8, 1);
    __syncthreads();
    uint32_t tbase;
    asm volatile("ld.shared.b32 %0, [%1];" : "=r"(tbase) : "r"(sb + 0));

#pragma unroll
    for (int c = 0; c < 2; c++) {
        uint32_t s = sb + SM_BUF + c * STG4_B;
        int k0 = c * 32;
        load_tile64(s,              P.Ah, m0, P.ldA, k0, tid);
        load_tile64(s + TILE_B,     P.Al, m0, P.ldA, k0, tid);
        load_tile64(s + 2 * TILE_B, P.Bh, n0, P.ldB, k0, tid);
        load_tile64(s + 3 * TILE_B, P.Bl, n0, P.ldB, k0, tid);
        cp_commit();
    }

    for (int k = 0; k < K; k++) {
        if (k + 2 < K) {
            if (k >= 1) mbar_wait(sb + 8 + ((k + 2) % 3) * 8, ((k - 1) / 3) & 1);
            uint32_t s = sb + SM_BUF + ((k + 2) % 3) * STG4_B;
            int k0 = (k + 2) * 32;
            load_tile64(s,              P.Ah, m0, P.ldA, k0, tid);
            load_tile64(s + TILE_B,     P.Al, m0, P.ldA, k0, tid);
            load_tile64(s + 2 * TILE_B, P.Bh, n0, P.ldB, k0, tid);
            load_tile64(s + 3 * TILE_B, P.Bl, n0, P.ldB, k0, tid);
            cp_commit();
            asm volatile("cp.async.wait_group 2;\n" ::: "memory");
        } else if (k + 1 < K) {
            asm volatile("cp.async.wait_group 1;\n" ::: "memory");
        } else {
            asm volatile("cp.async.wait_group 0;\n" ::: "memory");
        }
        __syncthreads();
        asm volatile("fence.proxy.async.shared::cta;" ::: "memory");

        if (wid == 0 && elect_one()) {
            uint32_t sc = sb + SM_BUF + (k % 3) * STG4_B;
            uint64_t ah = mkdesc64(sc);
            uint64_t al = mkdesc64(sc + TILE_B);
            uint64_t bh = mkdesc64(sc + 2 * TILE_B);
            uint64_t bl = mkdesc64(sc + 3 * TILE_B);
            bool first = (k == 0);
#pragma unroll
            for (int ks = 0; ks < 2; ks++)
                mma_f16kind_ss(tbase, ah + ks * 2, bh + ks * 2, IDESC_BF16, !(first && ks == 0));
#pragma unroll
            for (int ks = 0; ks < 2; ks++)
                mma_f16kind_ss(tbase, ah + ks * 2, bl + ks * 2, IDESC_BF16, true);
#pragma unroll
            for (int ks = 0; ks < 2; ks++)
                mma_f16kind_ss(tbase, al + ks * 2, bh + ks * 2, IDESC_BF16, true);
            tc_commit(sb + 8 + (k % 3) * 8);
        }
    }

    mbar_wait(sb + 8 + ((K - 1) % 3) * 8, ((K - 1) / 3) & 1);
    asm volatile("tcgen05.fence::after_thread_sync;" ::: "memory");

    const int sub = wid & 3;
    const int wg = wid >> 2;
    const int lane = tid & 31;
    const int row = m0 + sub * 32 + lane;

#pragma unroll
    for (int qi = 0; qi < 2; qi++) {
        const int q = wg * 2 + qi;
        uint32_t d[32];
        ldtm32(d, tbase + q * 32);
        asm volatile("tcgen05.wait::ld.sync.aligned;" ::: "memory");
        const int cbase = n0 + q * 32;

        if constexpr (EPI == 0) {
            float4* o = (float4*)(P.outF + (size_t)row * P.ldc + cbase);
#pragma unroll
            for (int jj = 0; jj < 8; jj++) {
                float4 v;
                v.x = __uint_as_float(d[jj * 4 + 0]);
                v.y = __uint_as_float(d[jj * 4 + 1]);
                v.z = __uint_as_float(d[jj * 4 + 2]);
                v.w = __uint_as_float(d[jj * 4 + 3]);
                o[jj] = v;
            }
        } else {
#pragma unroll
            for (int j = 0; j < 32; j++) {
                float val = __uint_as_float(d[j]);
                if (row == cbase + j) val -= 1.0f;
                __half h = __float2half(val);
                __half l = __float2half(val - __half2float(h));
                size_t idx = (size_t)row * NF + cbase + j;
                g_G16h[idx] = h;
                g_G16l[idx] = l;
            }
        }
    }

    asm volatile("tcgen05.fence::before_thread_sync;" ::: "memory");
    __syncthreads();
    if (wid == 0)
        asm volatile("tcgen05.dealloc.cta_group::1.sync.aligned.b32 %0, %1;"
                     :: "r"(tbase), "r"((uint32_t)BN));
#else
    (void)P;
#endif
}

// ---------------------------------------------------------------------------
// Persistent step kernel (steps 4..50, one launch) — R10 structure; act as
// SINGLE fp16 and G as fp16 h/l split => all-f16 MMAs (legal idesc), 4 MMAs
// per chunk instead of 6. Last step writes bf16 h/l act split (for full-
// precision recon) + fp32 acts directly into d_out. 2-stage, 50KB smem.
// ---------------------------------------------------------------------------
__global__ __launch_bounds__(NTHR, 2) void step_persistent(
    const __half* __restrict__ Gh, const __half* __restrict__ Gl,
    __half* __restrict__ afb,
    __nv_bfloat16* __restrict__ rh, __nv_bfloat16* __restrict__ rl,
    float* __restrict__ actOut)
{
#if TC_OK
    extern __shared__ char smem[];
    const uint32_t sb = smem_u32(smem);
    const int tid = threadIdx.x;
    const int wid = tid >> 5;
    const int m0 = blockIdx.y * 128, n0 = blockIdx.x * BN;
    const size_t NN = (size_t)NB * NF;
    const unsigned nCta = gridDim.x * gridDim.y;

    if (wid == 0) {
        asm volatile("tcgen05.alloc.cta_group::1.sync.aligned.shared::cta.b32 [%0], %1;"
                     :: "r"(sb + 0), "r"((uint32_t)BN) : "memory");
        asm volatile("tcgen05.relinquish_alloc_permit.cta_group::1.sync.aligned;");
    }
    if (tid < 2) mbar_init(sb + 8 + tid * 8, 1);
    __syncthreads();
    uint32_t tbase;
    asm volatile("ld.shared.b32 %0, [%1];" : "=r"(tbase) : "r"(sb + 0));

    unsigned nCommit[2] = {0u, 0u};

    for (int t = 4; t <= STEPS; t++) {
        const __half* Af = afb + (((t - 1) & 1) ? NN : 0);
        __half* Wf = afb + ((t & 1) ? NN : 0);
        const float c1 = 1.0f / (1.0f - powf(0.9f,   (float)t));
        const float c2 = 1.0f / (1.0f - powf(0.999f, (float)t));
        const bool last = (t == STEPS);

        // prologue: chunk 0 -> stage 0 (previous step's MMAs all complete)
        {
            uint32_t s = sb + SM_BUF;
            load_tile64(s,              Af, m0, NF, 0, tid);
            load_tile64(s + TILE_B,     Gh, n0, NF, 0, tid);
            load_tile64(s + 2 * TILE_B, Gl, n0, NF, 0, tid);
            cp_commit();
        }

        for (int k = 0; k < 32; k++) {
            const int s = k & 1;
            if (k + 1 < 32) {
                const int s2 = (k + 1) & 1;
                if (nCommit[s2] > 0)
                    mbar_wait(sb + 8 + s2 * 8, (nCommit[s2] - 1) & 1);
                uint32_t sa = sb + SM_BUF + s2 * STG3_B;
                int k0 = (k + 1) * 32;
                load_tile64(sa,              Af, m0, NF, k0, tid);
                load_tile64(sa + TILE_B,     Gh, n0, NF, k0, tid);
                load_tile64(sa + 2 * TILE_B, Gl, n0, NF, k0, tid);
                cp_commit();
                asm volatile("cp.async.wait_group 1;\n" ::: "memory");
            } else {
                asm volatile("cp.async.wait_group 0;\n" ::: "memory");
            }
            __syncthreads();
            asm volatile("fence.proxy.async.shared::cta;" ::: "memory");

            if (wid == 0 && elect_one()) {
                uint32_t sc = sb + SM_BUF + s * STG3_B;
                uint64_t af = mkdesc64(sc);
                uint64_t bh = mkdesc64(sc + TILE_B);
                uint64_t bl = mkdesc64(sc + 2 * TILE_B);
                bool first = (k == 0);
#pragma unroll
                for (int ks = 0; ks < 2; ks++)
                    mma_f16kind_ss(tbase, af + ks * 2, bh + ks * 2, IDESC_F16, !(first && ks == 0));
#pragma unroll
                for (int ks = 0; ks < 2; ks++)
                    mma_f16kind_ss(tbase, af + ks * 2, bl + ks * 2, IDESC_F16, true);
                tc_commit(sb + 8 + s * 8);
            }
            nCommit[s]++;
        }

        // wait for chunk 31 commit (stage 1); in-order => all MMAs done
        mbar_wait(sb + 8 + 8, (nCommit[1] - 1) & 1);
        asm volatile("tcgen05.fence::after_thread_sync;" ::: "memory");

        // AdamW epilogue
        const int sub = wid & 3;
        const int wg = wid >> 2;
        const int lane = tid & 31;
        const int row = m0 + sub * 32 + lane;

#pragma unroll
        for (int qi = 0; qi < 2; qi++) {
            const int q = wg * 2 + qi;
            uint32_t d[32];
            ldtm32(d, tbase + q * 32);
            asm volatile("tcgen05.wait::ld.sync.aligned;" ::: "memory");
            const int cbase = n0 + q * 32;
            const size_t base = (size_t)row * NF + cbase;
#pragma unroll
            for (int h2 = 0; h2 < 2; h2++) {
                float4 uo[4], mo[4], vo[4], ex[4];
#pragma unroll
                for (int j = 0; j < 4; j++) {
                    int jj = h2 * 4 + j;
                    uo[j] = *(const float4*)(g_u + base + jj * 4);
                    mo[j] = *(const float4*)(g_m + base + jj * 4);
                    vo[j] = *(const float4*)(g_v + base + jj * 4);
                    ex[j] = *(const float4*)(g_excite + base + jj * 4);
                }
#pragma unroll
                for (int j = 0; j < 4; j++) {
                    int jj = h2 * 4 + j;
                    float uoa[4] = {uo[j].x, uo[j].y, uo[j].z, uo[j].w};
                    float moa[4] = {mo[j].x, mo[j].y, mo[j].z, mo[j].w};
                    float voa[4] = {vo[j].x, vo[j].y, vo[j].z, vo[j].w};
                    float exa[4] = {ex[j].x, ex[j].y, ex[j].z, ex[j].w};
                    float4 mn4, vn4, un4;
                    float* mnp = &mn4.x; float* vnp = &vn4.x; float* unp = &un4.x;
                    float ac[4];
#pragma unroll
                    for (int c = 0; c < 4; c++) {
                        float sv = __uint_as_float(d[jj * 4 + c]);
                        float g = uoa[c] - exa[c] + sv;
                        float mn = 0.9f * moa[c] + 0.1f * g;
                        float vn = 0.999f * voa[c] + 0.001f * g * g;
                        float u2 = uoa[c] * (1.0f - LR * WD);
                        u2 -= LR * (mn * c1) / (sqrtf(vn * c2) + EPS);
                        mnp[c] = mn; vnp[c] = vn; unp[c] = u2;
                        ac[c] = fmaxf(u2 - SHRINK, 0.0f);
                    }
                    *(float4*)(g_u + base + jj * 4) = un4;
                    *(float4*)(g_m + base + jj * 4) = mn4;
                    *(float4*)(g_v + base + jj * 4) = vn4;
                    if (!last) {
                        *(__half2*)(Wf + base + jj * 4)     = __floats2half2_rn(ac[0], ac[1]);
                        *(__half2*)(Wf + base + jj * 4 + 2) = __floats2half2_rn(ac[2], ac[3]);
                    } else {
                        __nv_bfloat162 hh0, hh1, ll0, ll1;
                        hh0.x = __float2bfloat16(ac[0]); hh0.y = __float2bfloat16(ac[1]);
                        hh1.x = __float2bfloat16(ac[2]); hh1.y = __float2bfloat16(ac[3]);
                        ll0.x = __float2bfloat16(ac[0] - __bfloat162float(hh0.x));
                        ll0.y = __float2bfloat16(ac[1] - __bfloat162float(hh0.y));
                        ll1.x = __float2bfloat16(ac[2] - __bfloat162float(hh1.x));
                        ll1.y = __float2bfloat16(ac[3] - __bfloat162float(hh1.y));
                        *(__nv_bfloat162*)(rh + base + jj * 4) = hh0;
                        *(__nv_bfloat162*)(rh + base + jj * 4 + 2) = hh1;
                        *(__nv_bfloat162*)(rl + base + jj * 4) = ll0;
                        *(__nv_bfloat162*)(rl + base + jj * 4 + 2) = ll1;
                        float4 a4; a4.x = ac[0]; a4.y = ac[1]; a4.z = ac[2]; a4.w = ac[3];
                        *(float4*)(actOut + base + jj * 4) = a4;
                    }
                }
            }
        }
        asm volatile("tcgen05.fence::before_thread_sync;" ::: "memory");

        if (!last) {
            __threadfence();
            __syncthreads();
            if (tid == 0) {
                atomicAdd(&g_bar, 1u);
                const unsigned target = (unsigned)(t - 3) * nCta;
                unsigned v;
                do {
                    asm volatile("ld.global.acquire.gpu.b32 %0, [%1];"
                                 : "=r"(v) : "l"(&g_bar));
                    if (v >= target) break;
                    __nanosleep(128);
                } while (true);
            }
            __syncthreads();
        }
    }

    __syncthreads();
    if (wid == 0)
        asm volatile("tcgen05.dealloc.cta_group::1.sync.aligned.b32 %0, %1;"
                     :: "r"(tbase), "r"((uint32_t)BN));
#else
    (void)Gh; (void)Gl; (void)afb; (void)rh; (void)rl; (void)actOut;
#endif
}

// ---------------- fused elementwise AdamW steps 1..3 ------------------------
__global__ void k_step_ew3(float c11, float c21, float c12, float c22,
                           float c13, float c23, __half* __restrict__ awf) {
    size_t i4 = (size_t)blockIdx.x * blockDim.x + threadIdx.x;
    if (i4 == 0) g_bar = 0u;
    if (i4 >= (size_t)NB * NF / 4) return;
    float4 ex4 = ((const float4*)g_excite)[i4];
    float exa[4] = {ex4.x, ex4.y, ex4.z, ex4.w};
    float4 un4, mn4, vn4;
    float* unp = &un4.x; float* mnp = &mn4.x; float* vnp = &vn4.x;
    size_t b = i4 * 4;
    float acv[4];
#pragma unroll
    for (int c = 0; c < 4; c++) {
        float u = 0.f, m = 0.f, v = 0.f;
        float cc1[3] = {c11, c12, c13};
        float cc2[3] = {c21, c22, c23};
#pragma unroll
        for (int t = 0; t < 3; t++) {
            float g = u - exa[c];
            m = 0.9f * m + 0.1f * g;
            v = 0.999f * v + 0.001f * g * g;
            u = u * (1.0f - LR * WD);
            u -= LR * (m * cc1[t]) / (sqrtf(v * cc2[t]) + EPS);
        }
        unp[c] = u; mnp[c] = m; vnp[c] = v;
        acv[c] = fmaxf(u - SHRINK, 0.0f);
    }
    ((float4*)g_u)[i4] = un4;
    ((float4*)g_m)[i4] = mn4;
    ((float4*)g_v)[i4] = vn4;
    *(__half2*)(awf + b)     = __floats2half2_rn(acv[0], acv[1]);
    *(__half2*)(awf + b + 2) = __floats2half2_rn(acv[2], acv[3]);
}

// ---------------- converts ---------------------------------------------------
__global__ void k_conv_img(const float* __restrict__ img) {
    size_t i = (size_t)blockIdx.x * blockDim.x + threadIdx.x;
    if (i < (size_t)NB * NP) {
        float x = img[i];
        __nv_bfloat16 h = __float2bfloat16(x);
        g_imgh[i] = h;
        g_imgl[i] = __float2bfloat16(x - __bfloat162float(h));
    }
}

__global__ void k_conv_phi(const float* __restrict__ f) {
    __shared__ float tile[32][33];
    int c0 = blockIdx.x * 32, p0 = blockIdx.y * 32;
    int tx = threadIdx.x, ty = threadIdx.y;
#pragma unroll
    for (int i = ty; i < 32; i += 8) {
        float x = f[(size_t)(p0 + i) * NF + c0 + tx];
        tile[i][tx] = x;
        __nv_bfloat16 h = __float2bfloat16(x);
        size_t idx = (size_t)(p0 + i) * NF + c0 + tx;
        g_phih[idx] = h;
        g_phil[idx] = __float2bfloat16(x - __bfloat162float(h));
    }
    __syncthreads();
#pragma unroll
    for (int i = ty; i < 32; i += 8) {
        float x = tile[tx][i];
        __nv_bfloat16 h = __float2bfloat16(x);
        size_t idx = (size_t)(c0 + i) * NP + p0 + tx;
        g_phith[idx] = h;
        g_phitl[idx] = __float2bfloat16(x - __bfloat162float(h));
    }
}

// ---------------- launcher ---------------------------------------------------
extern "C" void kernel_launch(void* const* d_in, const int* in_sizes, int n_in,
                              void* d_out, int out_size) {
    const float* images  = (const float*)d_in[0];
    const float* filters = (const float*)d_in[1];
    if (in_sizes[0] == NP * NF && in_sizes[1] == NB * NP) {
        filters = (const float*)d_in[0];
        images  = (const float*)d_in[1];
    }
    float* out = (float*)d_out;

    cudaFuncSetAttribute(mma_gemm<0>, cudaFuncAttributeMaxDynamicSharedMemorySize, SMEM_STANDALONE);
    cudaFuncSetAttribute(mma_gemm<1>, cudaFuncAttributeMaxDynamicSharedMemorySize, SMEM_STANDALONE);
    cudaFuncSetAttribute(step_persistent, cudaFuncAttributeMaxDynamicSharedMemorySize, SMEM_PERSIST);

    const __nv_bfloat16 *imgh, *imgl, *phih, *phil, *phith, *phitl;
    __nv_bfloat16 *acth, *actl;
    __half *af16, *G16h, *G16l;
    float *excite;
    cudaGetSymbolAddress((void**)&imgh, g_imgh);
    cudaGetSymbolAddress((void**)&imgl, g_imgl);
    cudaGetSymbolAddress((void**)&phih, g_phih);
    cudaGetSymbolAddress((void**)&phil, g_phil);
    cudaGetSymbolAddress((void**)&phith, g_phith);
    cudaGetSymbolAddress((void**)&phitl, g_phitl);
    cudaGetSymbolAddress((void**)&G16h, g_G16h);
    cudaGetSymbolAddress((void**)&G16l, g_G16l);
    cudaGetSymbolAddress((void**)&acth, g_acth);
    cudaGetSymbolAddress((void**)&actl, g_actl);
    cudaGetSymbolAddress((void**)&af16, g_af16);
    cudaGetSymbolAddress((void**)&excite, g_excite);
    float* actOut = out + (size_t)NB * NP;

    {
        size_t n = (size_t)NB * NP;
        k_conv_img<<<(unsigned)((n + 255) / 256), 256>>>(images);
    }
    k_conv_phi<<<dim3(NF / 32, NP / 32), dim3(32, 8)>>>(filters);

    // G = Phi^T Phi - I  (fp16 h/l split output)
    {
        GP p{};
        p.Ah = phith; p.Al = phitl; p.Bh = phith; p.Bl = phitl;
        p.ldA = NP; p.ldB = NP; p.kIters = NP / 32;
        mma_gemm<1><<<dim3(NF / BN, NF / 128), NTHR, SMEM_STANDALONE>>>(p);
    }

    // excite = images @ Phi
    {
        GP p{};
        p.Ah = imgh; p.Al = imgl; p.Bh = phith; p.Bl = phitl;
        p.ldA = NP; p.ldB = NP; p.kIters = NP / 32;
        p.outF = excite; p.ldc = NF;
        mma_gemm<0><<<dim3(NF / BN, NB / 128), NTHR, SMEM_STANDALONE>>>(p);
    }

    // steps 1..3 fused elementwise (act provably 0); also resets g_bar
    double b1t = 1.0, b2t = 1.0;
    float c1s[3], c2s[3];
    for (int t = 0; t < 3; t++) {
        b1t *= 0.9; b2t *= 0.999;
        c1s[t] = (float)(1.0 / (1.0 - b1t));
        c2s[t] = (float)(1.0 / (1.0 - b2t));
    }
    {
        unsigned ewg = (unsigned)(((size_t)NB * NF / 4 + 255) / 256);
        k_step_ew3<<<ewg, 256>>>(c1s[0], c2s[0], c1s[1], c2s[1], c1s[2], c2s[2],
                                 af16 + NBNF);   // t=3 -> buf 1
    }

    // steps 4..50 in ONE persistent launch; last step -> bf16 split + d_out
    step_persistent<<<dim3(NF / BN, NB / 128), NTHR, SMEM_PERSIST>>>(
        G16h, G16l, af16, acth, actl, actOut);

    // recon = act @ Phi^T -> d_out (full bf16 split act, full precision)
    {
        GP p{};
        p.Ah = acth; p.Al = actl;
        p.Bh = phih; p.Bl = phil;
        p.ldA = NF; p.ldB = NF; p.kIters = NF / 32;
        p.outF = out; p.ldc = NP;
        mma_gemm<0><<<dim3(NP / BN, NB / 128), NTHR, SMEM_STANDALONE>>>(p);
    }
}

// round 16
// speedup vs baseline: 1.4231x; 1.0975x over previous
#include <cuda_runtime.h>
#include <cuda_bf16.h>
#include <cuda_fp16.h>
#include <stdint.h>
#include <math.h>

#define NB 4096
#define NP 4096
#define NF 1024
#define SHRINK 0.25f
#define LR 0.1f
#define EPS 1e-8f
#define WD 1e-2f
#define STEPS 50

#if defined(__CUDA_ARCH_FEAT_SM103_ALL) || defined(__CUDA_ARCH_FEAT_SM100_ALL) || \
    defined(__CUDA_ARCH_FEAT_SM101_ALL) || defined(__CUDA_ARCH_FEAT_SM120_ALL)
#define TC_OK 1
#else
#define TC_OK 0
#endif

#define NTHR 256
#define BN 128

static const size_t NBNF = (size_t)NB * NF;

// ---------------- persistent device state ----------------------------------
__device__ float g_u[(size_t)NB * NF];
__device__ float g_m[(size_t)NB * NF];
__device__ float g_v[(size_t)NB * NF];
__device__ float g_excite[(size_t)NB * NF];
__device__ __half g_af16[2][(size_t)NB * NF];        // iteration act, fp16 ping-pong
__device__ __nv_bfloat16 g_acth[(size_t)NB * NF];    // final act bf16 split (recon)
__device__ __nv_bfloat16 g_actl[(size_t)NB * NF];
__device__ __nv_bfloat16 g_imgh[(size_t)NB * NP];
__device__ __nv_bfloat16 g_imgl[(size_t)NB * NP];
__device__ __nv_bfloat16 g_phih[(size_t)NP * NF];
__device__ __nv_bfloat16 g_phil[(size_t)NP * NF];
__device__ __nv_bfloat16 g_phith[(size_t)NF * NP];
__device__ __nv_bfloat16 g_phitl[(size_t)NF * NP];
__device__ __half g_G16[(size_t)NF * NF];            // G single fp16 (step GEMM)
__device__ unsigned int g_bar;   // grid-barrier counter (reset each call)

// ---------------- PTX helpers ----------------------------------------------
__device__ __forceinline__ uint32_t smem_u32(const void* p) {
    uint32_t a;
    asm("{ .reg .u64 t; cvta.to.shared.u64 t, %1; cvt.u32.u64 %0, t; }"
        : "=r"(a) : "l"(p));
    return a;
}
__device__ __forceinline__ uint32_t elect_one() {
    uint32_t p;
    asm volatile("{\n\t.reg .pred p;\n\telect.sync _|p, 0xFFFFFFFF;\n\t"
                 "selp.b32 %0, 1, 0, p;\n\t}" : "=r"(p));
    return p;
}
__device__ __forceinline__ void cp_async16(uint32_t dst, const void* src) {
    asm volatile("cp.async.cg.shared.global [%0], [%1], 16;\n" :: "r"(dst), "l"(src));
}
__device__ __forceinline__ void cp_commit() {
    asm volatile("cp.async.commit_group;\n" ::: "memory");
}
// SW64 descriptor: layout=4, version=1 (Blackwell), SBO=32 (512B atom), LBO=1
__device__ __forceinline__ uint64_t mkdesc64(uint32_t addr) {
    return ((uint64_t)4 << 61) | ((uint64_t)1 << 46) | ((uint64_t)32 << 32) |
           ((uint64_t)1 << 16) | ((uint64_t)(addr >> 4) & 0x3FFF);
}
__device__ __forceinline__ void mma_f16kind_ss(uint32_t d_tmem, uint64_t a_desc,
                                               uint64_t b_desc, uint32_t idesc, bool acc) {
    uint32_t en = acc ? 1u : 0u;
    asm volatile(
        "{\n\t.reg .pred p;\n\tsetp.ne.u32 p, %5, 0;\n\t"
        "tcgen05.mma.cta_group::1.kind::f16 [%0], %1, %2, %3, {%4,%4,%4,%4}, p;\n\t}"
        :: "r"(d_tmem), "l"(a_desc), "l"(b_desc), "r"(idesc), "r"(0u), "r"(en)
        : "memory");
}
__device__ __forceinline__ void mbar_init(uint32_t a, uint32_t cnt) {
    asm volatile("mbarrier.init.shared.b64 [%0], %1;" :: "r"(a), "r"(cnt) : "memory");
}
__device__ __forceinline__ void mbar_wait(uint32_t a, uint32_t phase) {
    asm volatile(
        "{\n\t.reg .pred P;\n\tLW%=:\n\t"
        "mbarrier.try_wait.parity.shared.b64 P, [%0], %1;\n\t"
        "@!P bra LW%=;\n\t}" :: "r"(a), "r"(phase) : "memory");
}
__device__ __forceinline__ void tc_commit(uint32_t mbar) {
    asm volatile(
        "tcgen05.commit.cta_group::1.mbarrier::arrive::one.shared::cluster.b64 [%0];"
        :: "r"(mbar) : "memory");
}
__device__ __forceinline__ void ldtm32(uint32_t (&r)[32], uint32_t a) {
    asm volatile(
        "tcgen05.ld.sync.aligned.32x32b.x32.b32 "
        "{%0,%1,%2,%3,%4,%5,%6,%7,%8,%9,%10,%11,%12,%13,%14,%15,"
        "%16,%17,%18,%19,%20,%21,%22,%23,%24,%25,%26,%27,%28,%29,%30,%31}, [%32];"
        : "=r"(r[0]), "=r"(r[1]), "=r"(r[2]), "=r"(r[3]), "=r"(r[4]), "=r"(r[5]),
          "=r"(r[6]), "=r"(r[7]), "=r"(r[8]), "=r"(r[9]), "=r"(r[10]), "=r"(r[11]),
          "=r"(r[12]), "=r"(r[13]), "=r"(r[14]), "=r"(r[15]), "=r"(r[16]),
          "=r"(r[17]), "=r"(r[18]), "=r"(r[19]), "=r"(r[20]), "=r"(r[21]),
          "=r"(r[22]), "=r"(r[23]), "=r"(r[24]), "=r"(r[25]), "=r"(r[26]),
          "=r"(r[27]), "=r"(r[28]), "=r"(r[29]), "=r"(r[30]), "=r"(r[31])
        : "r"(a));
}

// smem: [0..4) tmem ptr, [8..32) mbars, [1024..) stages
#define SM_BUF 1024
#define TILE_B 8192                        // 128 rows x 64B (SW64)
#define STG4_B (4 * TILE_B)                // standalone: Ah, Al, Bh, Bl
#define STG2_B (2 * TILE_B)                // step: Af16, G16
#define SMEM_STANDALONE (SM_BUF + 3 * STG4_B)   // 99328 (3-stage, R8-proven)
#define SMEM_PERSIST    (SM_BUF + 2 * STG2_B)   // 33792 (2-stage)
// idesc: F32 acc (bit4), atype bits[7:9], btype bits[10:12] (F16=0, BF16=1)
#define IDESC_BF16 0x8200490u   // A bf16, B bf16
#define IDESC_F16  0x8200010u   // A f16,  B f16

// Load 128-row x 32-col 2B-elem tile (64B/row), SW64 swizzled. NTHR threads.
__device__ __forceinline__ void load_tile64(uint32_t dst, const void* src,
                                            int row0, int ld, int k0, int tid) {
    const char* base = (const char*)src + ((size_t)row0 * ld + k0) * 2;
    const size_t ldb = (size_t)ld * 2;
#pragma unroll
    for (int i = 0; i < 512 / NTHR; i++) {
        int cg = tid + i * NTHR;            // 0..511
        int r = cg >> 2, c = cg & 3;        // 128 rows x 4 16B blocks
        uint32_t off = (uint32_t)(r * 64 + c * 16);
        uint32_t sw = off ^ ((off >> 3) & 0x30);
        cp_async16(dst + sw, base + (size_t)r * ldb + c * 16);
    }
}

struct GP {
    const __nv_bfloat16 *Ah, *Al, *Bh, *Bl;
    int ldA, ldB, kIters;
    float* outF; int ldc;             // EPI 0
};

// ---------------------------------------------------------------------------
// Standalone GEMM (R8-proven): 3-stage pipeline, full bf16 split (3 MMAs).
// EPI: 0 = fp32 store, 1 = G (-I, single fp16 out for the step kernel)
// ---------------------------------------------------------------------------
template <int EPI>
__global__ __launch_bounds__(NTHR) void mma_gemm(GP P) {
#if TC_OK
    extern __shared__ char smem[];
    const uint32_t sb = smem_u32(smem);
    const int tid = threadIdx.x;
    const int wid = tid >> 5;
    const int m0 = blockIdx.y * 128, n0 = blockIdx.x * BN;
    const int K = P.kIters;

    if (wid == 0) {
        asm volatile("tcgen05.alloc.cta_group::1.sync.aligned.shared::cta.b32 [%0], %1;"
                     :: "r"(sb + 0), "r"((uint32_t)BN) : "memory");
        asm volatile("tcgen05.relinquish_alloc_permit.cta_group::1.sync.aligned;");
    }
    if (tid < 3) mbar_init(sb + 8 + tid * 8, 1);
    __syncthreads();
    uint32_t tbase;
    asm volatile("ld.shared.b32 %0, [%1];" : "=r"(tbase) : "r"(sb + 0));

#pragma unroll
    for (int c = 0; c < 2; c++) {
        uint32_t s = sb + SM_BUF + c * STG4_B;
        int k0 = c * 32;
        load_tile64(s,              P.Ah, m0, P.ldA, k0, tid);
        load_tile64(s + TILE_B,     P.Al, m0, P.ldA, k0, tid);
        load_tile64(s + 2 * TILE_B, P.Bh, n0, P.ldB, k0, tid);
        load_tile64(s + 3 * TILE_B, P.Bl, n0, P.ldB, k0, tid);
        cp_commit();
    }

    for (int k = 0; k < K; k++) {
        if (k + 2 < K) {
            if (k >= 1) mbar_wait(sb + 8 + ((k + 2) % 3) * 8, ((k - 1) / 3) & 1);
            uint32_t s = sb + SM_BUF + ((k + 2) % 3) * STG4_B;
            int k0 = (k + 2) * 32;
            load_tile64(s,              P.Ah, m0, P.ldA, k0, tid);
            load_tile64(s + TILE_B,     P.Al, m0, P.ldA, k0, tid);
            load_tile64(s + 2 * TILE_B, P.Bh, n0, P.ldB, k0, tid);
            load_tile64(s + 3 * TILE_B, P.Bl, n0, P.ldB, k0, tid);
            cp_commit();
            asm volatile("cp.async.wait_group 2;\n" ::: "memory");
        } else if (k + 1 < K) {
            asm volatile("cp.async.wait_group 1;\n" ::: "memory");
        } else {
            asm volatile("cp.async.wait_group 0;\n" ::: "memory");
        }
        __syncthreads();
        asm volatile("fence.proxy.async.shared::cta;" ::: "memory");

        if (wid == 0 && elect_one()) {
            uint32_t sc = sb + SM_BUF + (k % 3) * STG4_B;
            uint64_t ah = mkdesc64(sc);
            uint64_t al = mkdesc64(sc + TILE_B);
            uint64_t bh = mkdesc64(sc + 2 * TILE_B);
            uint64_t bl = mkdesc64(sc + 3 * TILE_B);
            bool first = (k == 0);
#pragma unroll
            for (int ks = 0; ks < 2; ks++)
                mma_f16kind_ss(tbase, ah + ks * 2, bh + ks * 2, IDESC_BF16, !(first && ks == 0));
#pragma unroll
            for (int ks = 0; ks < 2; ks++)
                mma_f16kind_ss(tbase, ah + ks * 2, bl + ks * 2, IDESC_BF16, true);
#pragma unroll
            for (int ks = 0; ks < 2; ks++)
                mma_f16kind_ss(tbase, al + ks * 2, bh + ks * 2, IDESC_BF16, true);
            tc_commit(sb + 8 + (k % 3) * 8);
        }
    }

    mbar_wait(sb + 8 + ((K - 1) % 3) * 8, ((K - 1) / 3) & 1);
    asm volatile("tcgen05.fence::after_thread_sync;" ::: "memory");

    const int sub = wid & 3;
    const int wg = wid >> 2;
    const int lane = tid & 31;
    const int row = m0 + sub * 32 + lane;

#pragma unroll
    for (int qi = 0; qi < 2; qi++) {
        const int q = wg * 2 + qi;
        uint32_t d[32];
        ldtm32(d, tbase + q * 32);
        asm volatile("tcgen05.wait::ld.sync.aligned;" ::: "memory");
        const int cbase = n0 + q * 32;

        if constexpr (EPI == 0) {
            float4* o = (float4*)(P.outF + (size_t)row * P.ldc + cbase);
#pragma unroll
            for (int jj = 0; jj < 8; jj++) {
                float4 v;
                v.x = __uint_as_float(d[jj * 4 + 0]);
                v.y = __uint_as_float(d[jj * 4 + 1]);
                v.z = __uint_as_float(d[jj * 4 + 2]);
                v.w = __uint_as_float(d[jj * 4 + 3]);
                o[jj] = v;
            }
        } else {
#pragma unroll
            for (int j = 0; j < 32; j++) {
                float val = __uint_as_float(d[j]);
                if (row == cbase + j) val -= 1.0f;
                size_t idx = (size_t)row * NF + cbase + j;
                g_G16[idx] = __float2half(val);
            }
        }
    }

    asm volatile("tcgen05.fence::before_thread_sync;" ::: "memory");
    __syncthreads();
    if (wid == 0)
        asm volatile("tcgen05.dealloc.cta_group::1.sync.aligned.b32 %0, %1;"
                     :: "r"(tbase), "r"((uint32_t)BN));
#else
    (void)P;
#endif
}

// ---------------------------------------------------------------------------
// Persistent step kernel (steps 4..50, one launch): act fp16 single x G fp16
// single => 2 MMAs per K32 chunk. 2-stage, 33.8KB smem -> 2 CTAs/SM with a
// huge L1D carveout for optimizer state. Last step writes bf16 h/l act split
// (full-precision recon) + fp32 acts directly into d_out.
// ---------------------------------------------------------------------------
__global__ __launch_bounds__(NTHR, 2) void step_persistent(
    const __half* __restrict__ G16,
    __half* __restrict__ afb,
    __nv_bfloat16* __restrict__ rh, __nv_bfloat16* __restrict__ rl,
    float* __restrict__ actOut)
{
#if TC_OK
    extern __shared__ char smem[];
    const uint32_t sb = smem_u32(smem);
    const int tid = threadIdx.x;
    const int wid = tid >> 5;
    const int m0 = blockIdx.y * 128, n0 = blockIdx.x * BN;
    const size_t NN = (size_t)NB * NF;
    const unsigned nCta = gridDim.x * gridDim.y;

    if (wid == 0) {
        asm volatile("tcgen05.alloc.cta_group::1.sync.aligned.shared::cta.b32 [%0], %1;"
                     :: "r"(sb + 0), "r"((uint32_t)BN) : "memory");
        asm volatile("tcgen05.relinquish_alloc_permit.cta_group::1.sync.aligned;");
    }
    if (tid < 2) mbar_init(sb + 8 + tid * 8, 1);
    __syncthreads();
    uint32_t tbase;
    asm volatile("ld.shared.b32 %0, [%1];" : "=r"(tbase) : "r"(sb + 0));

    unsigned nCommit[2] = {0u, 0u};

    for (int t = 4; t <= STEPS; t++) {
        const __half* Af = afb + (((t - 1) & 1) ? NN : 0);
        __half* Wf = afb + ((t & 1) ? NN : 0);
        const float c1 = 1.0f / (1.0f - powf(0.9f,   (float)t));
        const float c2 = 1.0f / (1.0f - powf(0.999f, (float)t));
        const bool last = (t == STEPS);

        // prologue: chunk 0 -> stage 0 (previous step's MMAs all complete)
        {
            uint32_t s = sb + SM_BUF;
            load_tile64(s,          Af,  m0, NF, 0, tid);
            load_tile64(s + TILE_B, G16, n0, NF, 0, tid);
            cp_commit();
        }

        for (int k = 0; k < 32; k++) {
            const int s = k & 1;
            if (k + 1 < 32) {
                const int s2 = (k + 1) & 1;
                if (nCommit[s2] > 0)
                    mbar_wait(sb + 8 + s2 * 8, (nCommit[s2] - 1) & 1);
                uint32_t sa = sb + SM_BUF + s2 * STG2_B;
                int k0 = (k + 1) * 32;
                load_tile64(sa,          Af,  m0, NF, k0, tid);
                load_tile64(sa + TILE_B, G16, n0, NF, k0, tid);
                cp_commit();
                asm volatile("cp.async.wait_group 1;\n" ::: "memory");
            } else {
                asm volatile("cp.async.wait_group 0;\n" ::: "memory");
            }
            __syncthreads();
            asm volatile("fence.proxy.async.shared::cta;" ::: "memory");

            if (wid == 0 && elect_one()) {
                uint32_t sc = sb + SM_BUF + s * STG2_B;
                uint64_t af = mkdesc64(sc);
                uint64_t bg = mkdesc64(sc + TILE_B);
                bool first = (k == 0);
#pragma unroll
                for (int ks = 0; ks < 2; ks++)
                    mma_f16kind_ss(tbase, af + ks * 2, bg + ks * 2, IDESC_F16, !(first && ks == 0));
                tc_commit(sb + 8 + s * 8);
            }
            nCommit[s]++;
        }

        // wait for chunk 31 commit (stage 1); in-order => all MMAs done
        mbar_wait(sb + 8 + 8, (nCommit[1] - 1) & 1);
        asm volatile("tcgen05.fence::after_thread_sync;" ::: "memory");

        // AdamW epilogue
        const int sub = wid & 3;
        const int wg = wid >> 2;
        const int lane = tid & 31;
        const int row = m0 + sub * 32 + lane;

#pragma unroll
        for (int qi = 0; qi < 2; qi++) {
            const int q = wg * 2 + qi;
            uint32_t d[32];
            ldtm32(d, tbase + q * 32);
            asm volatile("tcgen05.wait::ld.sync.aligned;" ::: "memory");
            const int cbase = n0 + q * 32;
            const size_t base = (size_t)row * NF + cbase;
#pragma unroll
            for (int h2 = 0; h2 < 2; h2++) {
                float4 uo[4], mo[4], vo[4], ex[4];
#pragma unroll
                for (int j = 0; j < 4; j++) {
                    int jj = h2 * 4 + j;
                    uo[j] = *(const float4*)(g_u + base + jj * 4);
                    mo[j] = *(const float4*)(g_m + base + jj * 4);
                    vo[j] = *(const float4*)(g_v + base + jj * 4);
                    ex[j] = *(const float4*)(g_excite + base + jj * 4);
                }
#pragma unroll
                for (int j = 0; j < 4; j++) {
                    int jj = h2 * 4 + j;
                    float uoa[4] = {uo[j].x, uo[j].y, uo[j].z, uo[j].w};
                    float moa[4] = {mo[j].x, mo[j].y, mo[j].z, mo[j].w};
                    float voa[4] = {vo[j].x, vo[j].y, vo[j].z, vo[j].w};
                    float exa[4] = {ex[j].x, ex[j].y, ex[j].z, ex[j].w};
                    float4 mn4, vn4, un4;
                    float* mnp = &mn4.x; float* vnp = &vn4.x; float* unp = &un4.x;
                    float ac[4];
#pragma unroll
                    for (int c = 0; c < 4; c++) {
                        float sv = __uint_as_float(d[jj * 4 + c]);
                        float g = uoa[c] - exa[c] + sv;
                        float mn = 0.9f * moa[c] + 0.1f * g;
                        float vn = 0.999f * voa[c] + 0.001f * g * g;
                        float u2 = uoa[c] * (1.0f - LR * WD);
                        u2 -= LR * (mn * c1) / (sqrtf(vn * c2) + EPS);
                        mnp[c] = mn; vnp[c] = vn; unp[c] = u2;
                        ac[c] = fmaxf(u2 - SHRINK, 0.0f);
                    }
                    *(float4*)(g_u + base + jj * 4) = un4;
                    *(float4*)(g_m + base + jj * 4) = mn4;
                    *(float4*)(g_v + base + jj * 4) = vn4;
                    if (!last) {
                        *(__half2*)(Wf + base + jj * 4)     = __floats2half2_rn(ac[0], ac[1]);
                        *(__half2*)(Wf + base + jj * 4 + 2) = __floats2half2_rn(ac[2], ac[3]);
                    } else {
                        __nv_bfloat162 hh0, hh1, ll0, ll1;
                        hh0.x = __float2bfloat16(ac[0]); hh0.y = __float2bfloat16(ac[1]);
                        hh1.x = __float2bfloat16(ac[2]); hh1.y = __float2bfloat16(ac[3]);
                        ll0.x = __float2bfloat16(ac[0] - __bfloat162float(hh0.x));
                        ll0.y = __float2bfloat16(ac[1] - __bfloat162float(hh0.y));
                        ll1.x = __float2bfloat16(ac[2] - __bfloat162float(hh1.x));
                        ll1.y = __float2bfloat16(ac[3] - __bfloat162float(hh1.y));
                        *(__nv_bfloat162*)(rh + base + jj * 4) = hh0;
                        *(__nv_bfloat162*)(rh + base + jj * 4 + 2) = hh1;
                        *(__nv_bfloat162*)(rl + base + jj * 4) = ll0;
                        *(__nv_bfloat162*)(rl + base + jj * 4 + 2) = ll1;
                        float4 a4; a4.x = ac[0]; a4.y = ac[1]; a4.z = ac[2]; a4.w = ac[3];
                        *(float4*)(actOut + base + jj * 4) = a4;
                    }
                }
            }
        }
        asm volatile("tcgen05.fence::before_thread_sync;" ::: "memory");

        if (!last) {
            __threadfence();
            __syncthreads();
            if (tid == 0) {
                atomicAdd(&g_bar, 1u);
                const unsigned target = (unsigned)(t - 3) * nCta;
                unsigned v;
                do {
                    asm volatile("ld.global.acquire.gpu.b32 %0, [%1];"
                                 : "=r"(v) : "l"(&g_bar));
                    if (v >= target) break;
                    __nanosleep(128);
                } while (true);
            }
            __syncthreads();
        }
    }

    __syncthreads();
    if (wid == 0)
        asm volatile("tcgen05.dealloc.cta_group::1.sync.aligned.b32 %0, %1;"
                     :: "r"(tbase), "r"((uint32_t)BN));
#else
    (void)G16; (void)afb; (void)rh; (void)rl; (void)actOut;
#endif
}

// ---------------- fused elementwise AdamW steps 1..3 ------------------------
__global__ void k_step_ew3(float c11, float c21, float c12, float c22,
                           float c13, float c23, __half* __restrict__ awf) {
    size_t i4 = (size_t)blockIdx.x * blockDim.x + threadIdx.x;
    if (i4 == 0) g_bar = 0u;
    if (i4 >= (size_t)NB * NF / 4) return;
    float4 ex4 = ((const float4*)g_excite)[i4];
    float exa[4] = {ex4.x, ex4.y, ex4.z, ex4.w};
    float4 un4, mn4, vn4;
    float* unp = &un4.x; float* mnp = &mn4.x; float* vnp = &vn4.x;
    size_t b = i4 * 4;
    float acv[4];
#pragma unroll
    for (int c = 0; c < 4; c++) {
        float u = 0.f, m = 0.f, v = 0.f;
        float cc1[3] = {c11, c12, c13};
        float cc2[3] = {c21, c22, c23};
#pragma unroll
        for (int t = 0; t < 3; t++) {
            float g = u - exa[c];
            m = 0.9f * m + 0.1f * g;
            v = 0.999f * v + 0.001f * g * g;
            u = u * (1.0f - LR * WD);
            u -= LR * (m * cc1[t]) / (sqrtf(v * cc2[t]) + EPS);
        }
        unp[c] = u; mnp[c] = m; vnp[c] = v;
        acv[c] = fmaxf(u - SHRINK, 0.0f);
    }
    ((float4*)g_u)[i4] = un4;
    ((float4*)g_m)[i4] = mn4;
    ((float4*)g_v)[i4] = vn4;
    *(__half2*)(awf + b)     = __floats2half2_rn(acv[0], acv[1]);
    *(__half2*)(awf + b + 2) = __floats2half2_rn(acv[2], acv[3]);
}

// ---------------- converts ---------------------------------------------------
__global__ void k_conv_img(const float* __restrict__ img) {
    size_t i = (size_t)blockIdx.x * blockDim.x + threadIdx.x;
    if (i < (size_t)NB * NP) {
        float x = img[i];
        __nv_bfloat16 h = __float2bfloat16(x);
        g_imgh[i] = h;
        g_imgl[i] = __float2bfloat16(x - __bfloat162float(h));
    }
}

__global__ void k_conv_phi(const float* __restrict__ f) {
    __shared__ float tile[32][33];
    int c0 = blockIdx.x * 32, p0 = blockIdx.y * 32;
    int tx = threadIdx.x, ty = threadIdx.y;
#pragma unroll
    for (int i = ty; i < 32; i += 8) {
        float x = f[(size_t)(p0 + i) * NF + c0 + tx];
        tile[i][tx] = x;
        __nv_bfloat16 h = __float2bfloat16(x);
        size_t idx = (size_t)(p0 + i) * NF + c0 + tx;
        g_phih[idx] = h;
        g_phil[idx] = __float2bfloat16(x - __bfloat162float(h));
    }
    __syncthreads();
#pragma unroll
    for (int i = ty; i < 32; i += 8) {
        float x = tile[tx][i];
        __nv_bfloat16 h = __float2bfloat16(x);
        size_t idx = (size_t)(c0 + i) * NP + p0 + tx;
        g_phith[idx] = h;
        g_phitl[idx] = __float2bfloat16(x - __bfloat162float(h));
    }
}

// ---------------- launcher ---------------------------------------------------
extern "C" void kernel_launch(void* const* d_in, const int* in_sizes, int n_in,
                              void* d_out, int out_size) {
    const float* images  = (const float*)d_in[0];
    const float* filters = (const float*)d_in[1];
    if (in_sizes[0] == NP * NF && in_sizes[1] == NB * NP) {
        filters = (const float*)d_in[0];
        images  = (const float*)d_in[1];
    }
    float* out = (float*)d_out;

    cudaFuncSetAttribute(mma_gemm<0>, cudaFuncAttributeMaxDynamicSharedMemorySize, SMEM_STANDALONE);
    cudaFuncSetAttribute(mma_gemm<1>, cudaFuncAttributeMaxDynamicSharedMemorySize, SMEM_STANDALONE);
    cudaFuncSetAttribute(step_persistent, cudaFuncAttributeMaxDynamicSharedMemorySize, SMEM_PERSIST);

    const __nv_bfloat16 *imgh, *imgl, *phih, *phil, *phith, *phitl;
    __nv_bfloat16 *acth, *actl;
    __half *af16, *G16;
    float *excite;
    cudaGetSymbolAddress((void**)&imgh, g_imgh);
    cudaGetSymbolAddress((void**)&imgl, g_imgl);
    cudaGetSymbolAddress((void**)&phih, g_phih);
    cudaGetSymbolAddress((void**)&phil, g_phil);
    cudaGetSymbolAddress((void**)&phith, g_phith);
    cudaGetSymbolAddress((void**)&phitl, g_phitl);
    cudaGetSymbolAddress((void**)&G16, g_G16);
    cudaGetSymbolAddress((void**)&acth, g_acth);
    cudaGetSymbolAddress((void**)&actl, g_actl);
    cudaGetSymbolAddress((void**)&af16, g_af16);
    cudaGetSymbolAddress((void**)&excite, g_excite);
    float* actOut = out + (size_t)NB * NP;

    {
        size_t n = (size_t)NB * NP;
        k_conv_img<<<(unsigned)((n + 255) / 256), 256>>>(images);
    }
    k_conv_phi<<<dim3(NF / 32, NP / 32), dim3(32, 8)>>>(filters);

    // G = Phi^T Phi - I  (single fp16 output)
    {
        GP p{};
        p.Ah = phith; p.Al = phitl; p.Bh = phith; p.Bl = phitl;
        p.ldA = NP; p.ldB = NP; p.kIters = NP / 32;
        mma_gemm<1><<<dim3(NF / BN, NF / 128), NTHR, SMEM_STANDALONE>>>(p);
    }

    // excite = images @ Phi
    {
        GP p{};
        p.Ah = imgh; p.Al = imgl; p.Bh = phith; p.Bl = phitl;
        p.ldA = NP; p.ldB = NP; p.kIters = NP / 32;
        p.outF = excite; p.ldc = NF;
        mma_gemm<0><<<dim3(NF / BN, NB / 128), NTHR, SMEM_STANDALONE>>>(p);
    }

    // steps 1..3 fused elementwise (act provably 0); also resets g_bar
    double b1t = 1.0, b2t = 1.0;
    float c1s[3], c2s[3];
    for (int t = 0; t < 3; t++) {
        b1t *= 0.9; b2t *= 0.999;
        c1s[t] = (float)(1.0 / (1.0 - b1t));
        c2s[t] = (float)(1.0 / (1.0 - b2t));
    }
    {
        unsigned ewg = (unsigned)(((size_t)NB * NF / 4 + 255) / 256);
        k_step_ew3<<<ewg, 256>>>(c1s[0], c2s[0], c1s[1], c2s[1], c1s[2], c2s[2],
                                 af16 + NBNF);   // t=3 -> buf 1
    }

    // steps 4..50 in ONE persistent launch; last step -> bf16 split + d_out
    step_persistent<<<dim3(NF / BN, NB / 128), NTHR, SMEM_PERSIST>>>(
        G16, af16, acth, actl, actOut);

    // recon = act @ Phi^T -> d_out (full bf16 split act, full precision)
    {
        GP p{};
        p.Ah = acth; p.Al = actl;
        p.Bh = phih; p.Bl = phil;
        p.ldA = NF; p.ldB = NF; p.kIters = NF / 32;
        p.outF = out; p.ldc = NP;
        mma_gemm<0><<<dim3(NP / BN, NB / 128), NTHR, SMEM_STANDALONE>>>(p);
    }
}

// round 17
// speedup vs baseline: 1.5147x; 1.0644x over previous
#include <cuda_runtime.h>
#include <cuda_bf16.h>
#include <cuda_fp16.h>
#include <stdint.h>
#include <math.h>

#define NB 4096
#define NP 4096
#define NF 1024
#define SHRINK 0.25f
#define LR 0.1f
#define EPS 1e-8f
#define WD 1e-2f
#define STEPS 50

#if defined(__CUDA_ARCH_FEAT_SM103_ALL) || defined(__CUDA_ARCH_FEAT_SM100_ALL) || \
    defined(__CUDA_ARCH_FEAT_SM101_ALL) || defined(__CUDA_ARCH_FEAT_SM120_ALL)
#define TC_OK 1
#else
#define TC_OK 0
#endif

#define NTHR 256
#define BN 128

static const size_t NBNF = (size_t)NB * NF;

// ---------------- persistent device state ----------------------------------
__device__ float g_u[(size_t)NB * NF];
__device__ float g_m[(size_t)NB * NF];
__device__ float g_v[(size_t)NB * NF];
__device__ float g_excite[(size_t)NB * NF];
__device__ __half g_af16[2][(size_t)NB * NF];        // iteration act, fp16 ping-pong
__device__ __nv_bfloat16 g_acth[(size_t)NB * NF];    // final act bf16 split (recon)
__device__ __nv_bfloat16 g_actl[(size_t)NB * NF];
__device__ __nv_bfloat16 g_imgh[(size_t)NB * NP];
__device__ __nv_bfloat16 g_imgl[(size_t)NB * NP];
__device__ __nv_bfloat16 g_phih[(size_t)NP * NF];
__device__ __nv_bfloat16 g_phil[(size_t)NP * NF];
__device__ __nv_bfloat16 g_phith[(size_t)NF * NP];
__device__ __nv_bfloat16 g_phitl[(size_t)NF * NP];
__device__ __half g_G16[(size_t)NF * NF];            // G single fp16 (step GEMM)
__device__ unsigned int g_bar;   // grid-barrier counter (reset each call)

// ---------------- PTX helpers ----------------------------------------------
__device__ __forceinline__ uint32_t smem_u32(const void* p) {
    uint32_t a;
    asm("{ .reg .u64 t; cvta.to.shared.u64 t, %1; cvt.u32.u64 %0, t; }"
        : "=r"(a) : "l"(p));
    return a;
}
__device__ __forceinline__ uint32_t elect_one() {
    uint32_t p;
    asm volatile("{\n\t.reg .pred p;\n\telect.sync _|p, 0xFFFFFFFF;\n\t"
                 "selp.b32 %0, 1, 0, p;\n\t}" : "=r"(p));
    return p;
}
__device__ __forceinline__ void cp_async16(uint32_t dst, const void* src) {
    asm volatile("cp.async.cg.shared.global [%0], [%1], 16;\n" :: "r"(dst), "l"(src));
}
__device__ __forceinline__ void cp_commit() {
    asm volatile("cp.async.commit_group;\n" ::: "memory");
}
// SW64 descriptor: layout=4, version=1 (Blackwell), SBO=32 (512B atom), LBO=1
__device__ __forceinline__ uint64_t mkdesc64(uint32_t addr) {
    return ((uint64_t)4 << 61) | ((uint64_t)1 << 46) | ((uint64_t)32 << 32) |
           ((uint64_t)1 << 16) | ((uint64_t)(addr >> 4) & 0x3FFF);
}
// SW128 descriptor: layout=2, version=1, SBO=64 (1024B atom), LBO=1
__device__ __forceinline__ uint64_t mkdesc128(uint32_t addr) {
    return ((uint64_t)2 << 61) | ((uint64_t)1 << 46) | ((uint64_t)64 << 32) |
           ((uint64_t)1 << 16) | ((uint64_t)(addr >> 4) & 0x3FFF);
}
__device__ __forceinline__ void mma_f16kind_ss(uint32_t d_tmem, uint64_t a_desc,
                                               uint64_t b_desc, uint32_t idesc, bool acc) {
    uint32_t en = acc ? 1u : 0u;
    asm volatile(
        "{\n\t.reg .pred p;\n\tsetp.ne.u32 p, %5, 0;\n\t"
        "tcgen05.mma.cta_group::1.kind::f16 [%0], %1, %2, %3, {%4,%4,%4,%4}, p;\n\t}"
        :: "r"(d_tmem), "l"(a_desc), "l"(b_desc), "r"(idesc), "r"(0u), "r"(en)
        : "memory");
}
__device__ __forceinline__ void mbar_init(uint32_t a, uint32_t cnt) {
    asm volatile("mbarrier.init.shared.b64 [%0], %1;" :: "r"(a), "r"(cnt) : "memory");
}
__device__ __forceinline__ void mbar_wait(uint32_t a, uint32_t phase) {
    asm volatile(
        "{\n\t.reg .pred P;\n\tLW%=:\n\t"
        "mbarrier.try_wait.parity.shared.b64 P, [%0], %1;\n\t"
        "@!P bra LW%=;\n\t}" :: "r"(a), "r"(phase) : "memory");
}
__device__ __forceinline__ void tc_commit(uint32_t mbar) {
    asm volatile(
        "tcgen05.commit.cta_group::1.mbarrier::arrive::one.shared::cluster.b64 [%0];"
        :: "r"(mbar) : "memory");
}
__device__ __forceinline__ void ldtm32(uint32_t (&r)[32], uint32_t a) {
    asm volatile(
        "tcgen05.ld.sync.aligned.32x32b.x32.b32 "
        "{%0,%1,%2,%3,%4,%5,%6,%7,%8,%9,%10,%11,%12,%13,%14,%15,"
        "%16,%17,%18,%19,%20,%21,%22,%23,%24,%25,%26,%27,%28,%29,%30,%31}, [%32];"
        : "=r"(r[0]), "=r"(r[1]), "=r"(r[2]), "=r"(r[3]), "=r"(r[4]), "=r"(r[5]),
          "=r"(r[6]), "=r"(r[7]), "=r"(r[8]), "=r"(r[9]), "=r"(r[10]), "=r"(r[11]),
          "=r"(r[12]), "=r"(r[13]), "=r"(r[14]), "=r"(r[15]), "=r"(r[16]),
          "=r"(r[17]), "=r"(r[18]), "=r"(r[19]), "=r"(r[20]), "=r"(r[21]),
          "=r"(r[22]), "=r"(r[23]), "=r"(r[24]), "=r"(r[25]), "=r"(r[26]),
          "=r"(r[27]), "=r"(r[28]), "=r"(r[29]), "=r"(r[30]), "=r"(r[31])
        : "r"(a));
}

// smem: [0..4) tmem ptr, [8..32) mbars, [1024..) stages
#define SM_BUF 1024
#define TILE_B 8192                        // SW64 tile: 128 rows x 64B
#define TILE128_B 16384                    // SW128 tile: 128 rows x 128B
#define STG4_B (4 * TILE_B)                // standalone: Ah, Al, Bh, Bl (SW64)
#define STG2_B (2 * TILE128_B)             // step: Af16, G16 (SW128, K64)
#define SMEM_STANDALONE (SM_BUF + 3 * STG4_B)   // 99328 (3-stage, R8-proven)
#define SMEM_PERSIST    (SM_BUF + 2 * STG2_B)   // 66560 (2-stage, R10 footprint)
// idesc: F32 acc (bit4), atype bits[7:9], btype bits[10:12] (F16=0, BF16=1)
#define IDESC_BF16 0x8200490u   // A bf16, B bf16
#define IDESC_F16  0x8200010u   // A f16,  B f16

// Load 128-row x 32-col 2B tile (64B/row), SW64 swizzled. NTHR threads.
__device__ __forceinline__ void load_tile64(uint32_t dst, const void* src,
                                            int row0, int ld, int k0, int tid) {
    const char* base = (const char*)src + ((size_t)row0 * ld + k0) * 2;
    const size_t ldb = (size_t)ld * 2;
#pragma unroll
    for (int i = 0; i < 512 / NTHR; i++) {
        int cg = tid + i * NTHR;
        int r = cg >> 2, c = cg & 3;
        uint32_t off = (uint32_t)(r * 64 + c * 16);
        uint32_t sw = off ^ ((off >> 3) & 0x30);
        cp_async16(dst + sw, base + (size_t)r * ldb + c * 16);
    }
}

// Load 128-row x 64-col 2B tile (128B/row), SW128 swizzled. NTHR threads.
__device__ __forceinline__ void load_tile128(uint32_t dst, const void* src,
                                             int row0, int ld, int k0, int tid) {
    const char* base = (const char*)src + ((size_t)row0 * ld + k0) * 2;
    const size_t ldb = (size_t)ld * 2;
#pragma unroll
    for (int i = 0; i < 1024 / NTHR; i++) {
        int cg = tid + i * NTHR;            // 0..1023
        int r = cg >> 3, c = cg & 7;        // 128 rows x 8 16B blocks
        uint32_t off = (uint32_t)(r * 128 + c * 16);
        uint32_t sw = off ^ ((off >> 3) & 0x70);
        cp_async16(dst + sw, base + (size_t)r * ldb + c * 16);
    }
}

struct GP {
    const __nv_bfloat16 *Ah, *Al, *Bh, *Bl;
    int ldA, ldB, kIters;
    float* outF; int ldc;             // EPI 0
};

// ---------------------------------------------------------------------------
// Standalone GEMM (R8-proven): 3-stage pipeline, full bf16 split (3 MMAs).
// EPI: 0 = fp32 store, 1 = G (-I, single fp16 out for the step kernel)
// ---------------------------------------------------------------------------
template <int EPI>
__global__ __launch_bounds__(NTHR) void mma_gemm(GP P) {
#if TC_OK
    extern __shared__ char smem[];
    const uint32_t sb = smem_u32(smem);
    const int tid = threadIdx.x;
    const int wid = tid >> 5;
    const int m0 = blockIdx.y * 128, n0 = blockIdx.x * BN;
    const int K = P.kIters;

    if (wid == 0) {
        asm volatile("tcgen05.alloc.cta_group::1.sync.aligned.shared::cta.b32 [%0], %1;"
                     :: "r"(sb + 0), "r"((uint32_t)BN) : "memory");
        asm volatile("tcgen05.relinquish_alloc_permit.cta_group::1.sync.aligned;");
    }
    if (tid < 3) mbar_init(sb + 8 + tid * 8, 1);
    __syncthreads();
    uint32_t tbase;
    asm volatile("ld.shared.b32 %0, [%1];" : "=r"(tbase) : "r"(sb + 0));

#pragma unroll
    for (int c = 0; c < 2; c++) {
        uint32_t s = sb + SM_BUF + c * STG4_B;
        int k0 = c * 32;
        load_tile64(s,              P.Ah, m0, P.ldA, k0, tid);
        load_tile64(s + TILE_B,     P.Al, m0, P.ldA, k0, tid);
        load_tile64(s + 2 * TILE_B, P.Bh, n0, P.ldB, k0, tid);
        load_tile64(s + 3 * TILE_B, P.Bl, n0, P.ldB, k0, tid);
        cp_commit();
    }

    for (int k = 0; k < K; k++) {
        if (k + 2 < K) {
            if (k >= 1) mbar_wait(sb + 8 + ((k + 2) % 3) * 8, ((k - 1) / 3) & 1);
            uint32_t s = sb + SM_BUF + ((k + 2) % 3) * STG4_B;
            int k0 = (k + 2) * 32;
            load_tile64(s,              P.Ah, m0, P.ldA, k0, tid);
            load_tile64(s + TILE_B,     P.Al, m0, P.ldA, k0, tid);
            load_tile64(s + 2 * TILE_B, P.Bh, n0, P.ldB, k0, tid);
            load_tile64(s + 3 * TILE_B, P.Bl, n0, P.ldB, k0, tid);
            cp_commit();
            asm volatile("cp.async.wait_group 2;\n" ::: "memory");
        } else if (k + 1 < K) {
            asm volatile("cp.async.wait_group 1;\n" ::: "memory");
        } else {
            asm volatile("cp.async.wait_group 0;\n" ::: "memory");
        }
        __syncthreads();
        asm volatile("fence.proxy.async.shared::cta;" ::: "memory");

        if (wid == 0 && elect_one()) {
            uint32_t sc = sb + SM_BUF + (k % 3) * STG4_B;
            uint64_t ah = mkdesc64(sc);
            uint64_t al = mkdesc64(sc + TILE_B);
            uint64_t bh = mkdesc64(sc + 2 * TILE_B);
            uint64_t bl = mkdesc64(sc + 3 * TILE_B);
            bool first = (k == 0);
#pragma unroll
            for (int ks = 0; ks < 2; ks++)
                mma_f16kind_ss(tbase, ah + ks * 2, bh + ks * 2, IDESC_BF16, !(first && ks == 0));
#pragma unroll
            for (int ks = 0; ks < 2; ks++)
                mma_f16kind_ss(tbase, ah + ks * 2, bl + ks * 2, IDESC_BF16, true);
#pragma unroll
            for (int ks = 0; ks < 2; ks++)
                mma_f16kind_ss(tbase, al + ks * 2, bh + ks * 2, IDESC_BF16, true);
            tc_commit(sb + 8 + (k % 3) * 8);
        }
    }

    mbar_wait(sb + 8 + ((K - 1) % 3) * 8, ((K - 1) / 3) & 1);
    asm volatile("tcgen05.fence::after_thread_sync;" ::: "memory");

    const int sub = wid & 3;
    const int wg = wid >> 2;
    const int lane = tid & 31;
    const int row = m0 + sub * 32 + lane;

#pragma unroll
    for (int qi = 0; qi < 2; qi++) {
        const int q = wg * 2 + qi;
        uint32_t d[32];
        ldtm32(d, tbase + q * 32);
        asm volatile("tcgen05.wait::ld.sync.aligned;" ::: "memory");
        const int cbase = n0 + q * 32;

        if constexpr (EPI == 0) {
            float4* o = (float4*)(P.outF + (size_t)row * P.ldc + cbase);
#pragma unroll
            for (int jj = 0; jj < 8; jj++) {
                float4 v;
                v.x = __uint_as_float(d[jj * 4 + 0]);
                v.y = __uint_as_float(d[jj * 4 + 1]);
                v.z = __uint_as_float(d[jj * 4 + 2]);
                v.w = __uint_as_float(d[jj * 4 + 3]);
                o[jj] = v;
            }
        } else {
#pragma unroll
            for (int j = 0; j < 32; j++) {
                float val = __uint_as_float(d[j]);
                if (row == cbase + j) val -= 1.0f;
                size_t idx = (size_t)row * NF + cbase + j;
                g_G16[idx] = __float2half(val);
            }
        }
    }

    asm volatile("tcgen05.fence::before_thread_sync;" ::: "memory");
    __syncthreads();
    if (wid == 0)
        asm volatile("tcgen05.dealloc.cta_group::1.sync.aligned.b32 %0, %1;"
                     :: "r"(tbase), "r"((uint32_t)BN));
#else
    (void)P;
#endif
}

// ---------------------------------------------------------------------------
// Persistent step kernel (steps 4..50): act fp16 x G fp16, K=64 chunks in
// SW128 layout (16 chunks/step instead of 32 -> half the per-chunk sync and
// latency overhead). 4 MMAs (K16) per chunk. 2-stage, 66.5KB smem (R10-proven
// footprint). Last step writes bf16 h/l act split + fp32 acts into d_out.
// ---------------------------------------------------------------------------
__global__ __launch_bounds__(NTHR, 2) void step_persistent(
    const __half* __restrict__ G16,
    __half* __restrict__ afb,
    __nv_bfloat16* __restrict__ rh, __nv_bfloat16* __restrict__ rl,
    float* __restrict__ actOut)
{
#if TC_OK
    extern __shared__ char smem[];
    const uint32_t sb = smem_u32(smem);
    const int tid = threadIdx.x;
    const int wid = tid >> 5;
    const int m0 = blockIdx.y * 128, n0 = blockIdx.x * BN;
    const size_t NN = (size_t)NB * NF;
    const unsigned nCta = gridDim.x * gridDim.y;

    if (wid == 0) {
        asm volatile("tcgen05.alloc.cta_group::1.sync.aligned.shared::cta.b32 [%0], %1;"
                     :: "r"(sb + 0), "r"((uint32_t)BN) : "memory");
        asm volatile("tcgen05.relinquish_alloc_permit.cta_group::1.sync.aligned;");
    }
    if (tid < 2) mbar_init(sb + 8 + tid * 8, 1);
    __syncthreads();
    uint32_t tbase;
    asm volatile("ld.shared.b32 %0, [%1];" : "=r"(tbase) : "r"(sb + 0));

    unsigned nCommit[2] = {0u, 0u};

    for (int t = 4; t <= STEPS; t++) {
        const __half* Af = afb + (((t - 1) & 1) ? NN : 0);
        __half* Wf = afb + ((t & 1) ? NN : 0);
        const float c1 = 1.0f / (1.0f - powf(0.9f,   (float)t));
        const float c2 = 1.0f / (1.0f - powf(0.999f, (float)t));
        const bool last = (t == STEPS);

        // prologue: chunk 0 -> stage 0 (previous step's MMAs all complete)
        {
            uint32_t s = sb + SM_BUF;
            load_tile128(s,              Af,  m0, NF, 0, tid);
            load_tile128(s + TILE128_B,  G16, n0, NF, 0, tid);
            cp_commit();
        }

        for (int k = 0; k < 16; k++) {
            const int s = k & 1;
            if (k + 1 < 16) {
                const int s2 = (k + 1) & 1;
                if (nCommit[s2] > 0)
                    mbar_wait(sb + 8 + s2 * 8, (nCommit[s2] - 1) & 1);
                uint32_t sa = sb + SM_BUF + s2 * STG2_B;
                int k0 = (k + 1) * 64;
                load_tile128(sa,             Af,  m0, NF, k0, tid);
                load_tile128(sa + TILE128_B, G16, n0, NF, k0, tid);
                cp_commit();
                asm volatile("cp.async.wait_group 1;\n" ::: "memory");
            } else {
                asm volatile("cp.async.wait_group 0;\n" ::: "memory");
            }
            __syncthreads();
            asm volatile("fence.proxy.async.shared::cta;" ::: "memory");

            if (wid == 0 && elect_one()) {
                uint32_t sc = sb + SM_BUF + s * STG2_B;
                uint64_t af = mkdesc128(sc);
                uint64_t bg = mkdesc128(sc + TILE128_B);
                bool first = (k == 0);
#pragma unroll
                for (int ks = 0; ks < 4; ks++)
                    mma_f16kind_ss(tbase, af + ks * 2, bg + ks * 2, IDESC_F16, !(first && ks == 0));
                tc_commit(sb + 8 + s * 8);
            }
            nCommit[s]++;
        }

        // wait for chunk 15 commit (stage 1); in-order => all MMAs done
        mbar_wait(sb + 8 + 8, (nCommit[1] - 1) & 1);
        asm volatile("tcgen05.fence::after_thread_sync;" ::: "memory");

        // AdamW epilogue
        const int sub = wid & 3;
        const int wg = wid >> 2;
        const int lane = tid & 31;
        const int row = m0 + sub * 32 + lane;

#pragma unroll
        for (int qi = 0; qi < 2; qi++) {
            const int q = wg * 2 + qi;
            uint32_t d[32];
            ldtm32(d, tbase + q * 32);
            asm volatile("tcgen05.wait::ld.sync.aligned;" ::: "memory");
            const int cbase = n0 + q * 32;
            const size_t base = (size_t)row * NF + cbase;
#pragma unroll
            for (int h2 = 0; h2 < 2; h2++) {
                float4 uo[4], mo[4], vo[4], ex[4];
#pragma unroll
                for (int j = 0; j < 4; j++) {
                    int jj = h2 * 4 + j;
                    uo[j] = *(const float4*)(g_u + base + jj * 4);
                    mo[j] = *(const float4*)(g_m + base + jj * 4);
                    vo[j] = *(const float4*)(g_v + base + jj * 4);
                    ex[j] = *(const float4*)(g_excite + base + jj * 4);
                }
#pragma unroll
                for (int j = 0; j < 4; j++) {
                    int jj = h2 * 4 + j;
                    float uoa[4] = {uo[j].x, uo[j].y, uo[j].z, uo[j].w};
                    float moa[4] = {mo[j].x, mo[j].y, mo[j].z, mo[j].w};
                    float voa[4] = {vo[j].x, vo[j].y, vo[j].z, vo[j].w};
                    float exa[4] = {ex[j].x, ex[j].y, ex[j].z, ex[j].w};
                    float4 mn4, vn4, un4;
                    float* mnp = &mn4.x; float* vnp = &vn4.x; float* unp = &un4.x;
                    float ac[4];
#pragma unroll
                    for (int c = 0; c < 4; c++) {
                        float sv = __uint_as_float(d[jj * 4 + c]);
                        float g = uoa[c] - exa[c] + sv;
                        float mn = 0.9f * moa[c] + 0.1f * g;
                        float vn = 0.999f * voa[c] + 0.001f * g * g;
                        float u2 = uoa[c] * (1.0f - LR * WD);
                        u2 -= LR * (mn * c1) / (sqrtf(vn * c2) + EPS);
                        mnp[c] = mn; vnp[c] = vn; unp[c] = u2;
                        ac[c] = fmaxf(u2 - SHRINK, 0.0f);
                    }
                    *(float4*)(g_u + base + jj * 4) = un4;
                    *(float4*)(g_m + base + jj * 4) = mn4;
                    *(float4*)(g_v + base + jj * 4) = vn4;
                    if (!last) {
                        *(__half2*)(Wf + base + jj * 4)     = __floats2half2_rn(ac[0], ac[1]);
                        *(__half2*)(Wf + base + jj * 4 + 2) = __floats2half2_rn(ac[2], ac[3]);
                    } else {
                        __nv_bfloat162 hh0, hh1, ll0, ll1;
                        hh0.x = __float2bfloat16(ac[0]); hh0.y = __float2bfloat16(ac[1]);
                        hh1.x = __float2bfloat16(ac[2]); hh1.y = __float2bfloat16(ac[3]);
                        ll0.x = __float2bfloat16(ac[0] - __bfloat162float(hh0.x));
                        ll0.y = __float2bfloat16(ac[1] - __bfloat162float(hh0.y));
                        ll1.x = __float2bfloat16(ac[2] - __bfloat162float(hh1.x));
                        ll1.y = __float2bfloat16(ac[3] - __bfloat162float(hh1.y));
                        *(__nv_bfloat162*)(rh + base + jj * 4) = hh0;
                        *(__nv_bfloat162*)(rh + base + jj * 4 + 2) = hh1;
                        *(__nv_bfloat162*)(rl + base + jj * 4) = ll0;
                        *(__nv_bfloat162*)(rl + base + jj * 4 + 2) = ll1;
                        float4 a4; a4.x = ac[0]; a4.y = ac[1]; a4.z = ac[2]; a4.w = ac[3];
                        *(float4*)(actOut + base + jj * 4) = a4;
                    }
                }
            }
        }
        asm volatile("tcgen05.fence::before_thread_sync;" ::: "memory");

        if (!last) {
            __threadfence();
            __syncthreads();
            if (tid == 0) {
                atomicAdd(&g_bar, 1u);
                const unsigned target = (unsigned)(t - 3) * nCta;
                unsigned v;
                do {
                    asm volatile("ld.global.acquire.gpu.b32 %0, [%1];"
                                 : "=r"(v) : "l"(&g_bar));
                    if (v >= target) break;
                    __nanosleep(128);
                } while (true);
            }
            __syncthreads();
        }
    }

    __syncthreads();
    if (wid == 0)
        asm volatile("tcgen05.dealloc.cta_group::1.sync.aligned.b32 %0, %1;"
                     :: "r"(tbase), "r"((uint32_t)BN));
#else
    (void)G16; (void)afb; (void)rh; (void)rl; (void)actOut;
#endif
}

// ---------------- fused elementwise AdamW steps 1..3 ------------------------
__global__ void k_step_ew3(float c11, float c21, float c12, float c22,
                           float c13, float c23, __half* __restrict__ awf) {
    size_t i4 = (size_t)blockIdx.x * blockDim.x + threadIdx.x;
    if (i4 == 0) g_bar = 0u;
    if (i4 >= (size_t)NB * NF / 4) return;
    float4 ex4 = ((const float4*)g_excite)[i4];
    float exa[4] = {ex4.x, ex4.y, ex4.z, ex4.w};
    float4 un4, mn4, vn4;
    float* unp = &un4.x; float* mnp = &mn4.x; float* vnp = &vn4.x;
    size_t b = i4 * 4;
    float acv[4];
#pragma unroll
    for (int c = 0; c < 4; c++) {
        float u = 0.f, m = 0.f, v = 0.f;
        float cc1[3] = {c11, c12, c13};
        float cc2[3] = {c21, c22, c23};
#pragma unroll
        for (int t = 0; t < 3; t++) {
            float g = u - exa[c];
            m = 0.9f * m + 0.1f * g;
            v = 0.999f * v + 0.001f * g * g;
            u = u * (1.0f - LR * WD);
            u -= LR * (m * cc1[t]) / (sqrtf(v * cc2[t]) + EPS);
        }
        unp[c] = u; mnp[c] = m; vnp[c] = v;
        acv[c] = fmaxf(u - SHRINK, 0.0f);
    }
    ((float4*)g_u)[i4] = un4;
    ((float4*)g_m)[i4] = mn4;
    ((float4*)g_v)[i4] = vn4;
    *(__half2*)(awf + b)     = __floats2half2_rn(acv[0], acv[1]);
    *(__half2*)(awf + b + 2) = __floats2half2_rn(acv[2], acv[3]);
}

// ---------------- converts ---------------------------------------------------
__global__ void k_conv_img(const float* __restrict__ img) {
    size_t i = (size_t)blockIdx.x * blockDim.x + threadIdx.x;
    if (i < (size_t)NB * NP) {
        float x = img[i];
        __nv_bfloat16 h = __float2bfloat16(x);
        g_imgh[i] = h;
        g_imgl[i] = __float2bfloat16(x - __bfloat162float(h));
    }
}

__global__ void k_conv_phi(const float* __restrict__ f) {
    __shared__ float tile[32][33];
    int c0 = blockIdx.x * 32, p0 = blockIdx.y * 32;
    int tx = threadIdx.x, ty = threadIdx.y;
#pragma unroll
    for (int i = ty; i < 32; i += 8) {
        float x = f[(size_t)(p0 + i) * NF + c0 + tx];
        tile[i][tx] = x;
        __nv_bfloat16 h = __float2bfloat16(x);
        size_t idx = (size_t)(p0 + i) * NF + c0 + tx;
        g_phih[idx] = h;
        g_phil[idx] = __float2bfloat16(x - __bfloat162float(h));
    }
    __syncthreads();
#pragma unroll
    for (int i = ty; i < 32; i += 8) {
        float x = tile[tx][i];
        __nv_bfloat16 h = __float2bfloat16(x);
        size_t idx = (size_t)(c0 + i) * NP + p0 + tx;
        g_phith[idx] = h;
        g_phitl[idx] = __float2bfloat16(x - __bfloat162float(h));
    }
}

// ---------------- launcher ---------------------------------------------------
extern "C" void kernel_launch(void* const* d_in, const int* in_sizes, int n_in,
                              void* d_out, int out_size) {
    const float* images  = (const float*)d_in[0];
    const float* filters = (const float*)d_in[1];
    if (in_sizes[0] == NP * NF && in_sizes[1] == NB * NP) {
        filters = (const float*)d_in[0];
        images  = (const float*)d_in[1];
    }
    float* out = (float*)d_out;

    cudaFuncSetAttribute(mma_gemm<0>, cudaFuncAttributeMaxDynamicSharedMemorySize, SMEM_STANDALONE);
    cudaFuncSetAttribute(mma_gemm<1>, cudaFuncAttributeMaxDynamicSharedMemorySize, SMEM_STANDALONE);
    cudaFuncSetAttribute(step_persistent, cudaFuncAttributeMaxDynamicSharedMemorySize, SMEM_PERSIST);

    const __nv_bfloat16 *imgh, *imgl, *phih, *phil, *phith, *phitl;
    __nv_bfloat16 *acth, *actl;
    __half *af16, *G16;
    float *excite;
    cudaGetSymbolAddress((void**)&imgh, g_imgh);
    cudaGetSymbolAddress((void**)&imgl, g_imgl);
    cudaGetSymbolAddress((void**)&phih, g_phih);
    cudaGetSymbolAddress((void**)&phil, g_phil);
    cudaGetSymbolAddress((void**)&phith, g_phith);
    cudaGetSymbolAddress((void**)&phitl, g_phitl);
    cudaGetSymbolAddress((void**)&G16, g_G16);
    cudaGetSymbolAddress((void**)&acth, g_acth);
    cudaGetSymbolAddress((void**)&actl, g_actl);
    cudaGetSymbolAddress((void**)&af16, g_af16);
    cudaGetSymbolAddress((void**)&excite, g_excite);
    float* actOut = out + (size_t)NB * NP;

    {
        size_t n = (size_t)NB * NP;
        k_conv_img<<<(unsigned)((n + 255) / 256), 256>>>(images);
    }
    k_conv_phi<<<dim3(NF / 32, NP / 32), dim3(32, 8)>>>(filters);

    // G = Phi^T Phi - I  (single fp16 output)
    {
        GP p{};
        p.Ah = phith; p.Al = phitl; p.Bh = phith; p.Bl = phitl;
        p.ldA = NP; p.ldB = NP; p.kIters = NP / 32;
        mma_gemm<1><<<dim3(NF / BN, NF / 128), NTHR, SMEM_STANDALONE>>>(p);
    }

    // excite = images @ Phi
    {
        GP p{};
        p.Ah = imgh; p.Al = imgl; p.Bh = phith; p.Bl = phitl;
        p.ldA = NP; p.ldB = NP; p.kIters = NP / 32;
        p.outF = excite; p.ldc = NF;
        mma_gemm<0><<<dim3(NF / BN, NB / 128), NTHR, SMEM_STANDALONE>>>(p);
    }

    // steps 1..3 fused elementwise (act provably 0); also resets g_bar
    double b1t = 1.0, b2t = 1.0;
    float c1s[3], c2s[3];
    for (int t = 0; t < 3; t++) {
        b1t *= 0.9; b2t *= 0.999;
        c1s[t] = (float)(1.0 / (1.0 - b1t));
        c2s[t] = (float)(1.0 / (1.0 - b2t));
    }
    {
        unsigned ewg = (unsigned)(((size_t)NB * NF / 4 + 255) / 256);
        k_step_ew3<<<ewg, 256>>>(c1s[0], c2s[0], c1s[1], c2s[1], c1s[2], c2s[2],
                                 af16 + NBNF);   // t=3 -> buf 1
    }

    // steps 4..50 in ONE persistent launch; last step -> bf16 split + d_out
    step_persistent<<<dim3(NF / BN, NB / 128), NTHR, SMEM_PERSIST>>>(
        G16, af16, acth, actl, actOut);

    // recon = act @ Phi^T -> d_out (full bf16 split act, full precision)
    {
        GP p{};
        p.Ah = acth; p.Al = actl;
        p.Bh = phih; p.Bl = phil;
        p.ldA = NF; p.ldB = NF; p.kIters = NF / 32;
        p.outF = out; p.ldc = NP;
        mma_gemm<0><<<dim3(NP / BN, NB / 128), NTHR, SMEM_STANDALONE>>>(p);
    }
}